// round 1
// baseline (speedup 1.0000x reference)
#include <cuda_runtime.h>
#include <math.h>

#define TOK 4096     // B*S
#define EMB 1024     // E
#define SEQ 2048     // S
#define BSZ 2        // B
#define NH  16       // heads
#define HD  64       // head dim

// Scratch (device globals — allocation-free per harness rules)
__device__ float g_q[(size_t)TOK * EMB];  // [B,H,S,D]
__device__ float g_k[(size_t)TOK * EMB];  // [B,H,S,D]
__device__ float g_v[(size_t)TOK * EMB];  // [B,H,S,D]
__device__ float g_x[(size_t)TOK * EMB];  // [T,E] attention output (heads merged)

// ---------------------------------------------------------------------------
// C[M=4096, N=1024] = A @ W + bias
// DST: 0/1/2 -> g_q/g_k/g_v in head-split [B,H,S,D]; 3 -> Cout row-major [T,E]
// SRC_GX: read A from g_x instead of Ain (output projection)
// Tiling: 64x64 block, BK=16, 256 threads, 4x4 per-thread microtile.
// ---------------------------------------------------------------------------
template<int DST, bool SRC_GX>
__global__ __launch_bounds__(256)
void gemm64(const float* __restrict__ Ain, const float* __restrict__ W,
            const float* __restrict__ bias, float* __restrict__ Cout)
{
    const float* A = SRC_GX ? g_x : Ain;
    float* C = (DST == 0) ? g_q : (DST == 1) ? g_k : (DST == 2) ? g_v : Cout;

    __shared__ float As[16][68];   // As[k][m] (A transposed), pad 68 keeps 16B align
    __shared__ float Bs[16][68];   // Bs[k][n]

    const int tid = threadIdx.x;
    const int ty = tid >> 4, tx = tid & 15;
    const int m0 = blockIdx.y << 6, n0 = blockIdx.x << 6;

    // global-load assignments
    const int ar = tid >> 2;            // A row within tile (0..63)
    const int ac = (tid & 3) << 2;      // A col4 within 16-wide k-slab
    const int kr = tid >> 4;            // W k-row within slab (0..15)
    const int nc = (tid & 15) << 2;     // W col4 within 64-wide n-tile

    const float* Aptr = A + (size_t)(m0 + ar) * EMB + ac;
    const float* Wptr = W + (size_t)kr * EMB + n0 + nc;

    float acc[4][4] = {};
    for (int kk = 0; kk < EMB; kk += 16) {
        float4 a4 = *(const float4*)(Aptr + kk);
        float4 w4 = *(const float4*)(Wptr + (size_t)kk * EMB);
        As[ac + 0][ar] = a4.x; As[ac + 1][ar] = a4.y;
        As[ac + 2][ar] = a4.z; As[ac + 3][ar] = a4.w;
        *(float4*)&Bs[kr][nc] = w4;
        __syncthreads();
#pragma unroll
        for (int k = 0; k < 16; k++) {
            float4 a = *(const float4*)&As[k][ty << 2];
            float4 b = *(const float4*)&Bs[k][tx << 2];
            float av[4] = {a.x, a.y, a.z, a.w};
            float bv[4] = {b.x, b.y, b.z, b.w};
#pragma unroll
            for (int i = 0; i < 4; i++)
#pragma unroll
                for (int j = 0; j < 4; j++)
                    acc[i][j] = fmaf(av[i], bv[j], acc[i][j]);
        }
        __syncthreads();
    }

#pragma unroll
    for (int i = 0; i < 4; i++) {
        const int m = m0 + (ty << 2) + i;
#pragma unroll
        for (int j = 0; j < 4; j++) {
            const int n = n0 + (tx << 2) + j;
            const float val = acc[i][j] + bias[n];
            if (DST <= 2) {
                const int b = m >> 11, s = m & (SEQ - 1);
                const int h = n >> 6,  d = n & (HD - 1);
                C[(((size_t)b * NH + h) * SEQ + s) * HD + d] = val;
            } else {
                C[(size_t)m * EMB + n] = val;
            }
        }
    }
}

// ---------------------------------------------------------------------------
// Causal flash attention, fp32. One block = 64 query rows of one (b,h).
// 256 threads as 16x16; each thread owns a 4x4 microtile of the 64x64 score
// tile and the matching 4 rows x 4 cols of the O tile. Online softmax with
// shfl reductions across the 16 tx lanes (same-ty lanes share a warp half).
// ---------------------------------------------------------------------------
__global__ __launch_bounds__(256)
void attn_kernel()
{
    extern __shared__ float sm[];
    float (*Qs)[68] = (float(*)[68])(sm);              // Qs[d][i]  (Q^T, pre-scaled)
    float (*Ks)[68] = (float(*)[68])(sm + 64 * 68);    // Ks[d][j]  (K^T)
    float (*Vs)[68] = (float(*)[68])(sm + 2 * 64 * 68);// Vs[j][d]
    float (*Ps)[68] = (float(*)[68])(sm + 3 * 64 * 68);// Ps[j][i]  (P^T)

    const int tid = threadIdx.x;
    const int ty = tid >> 4, tx = tid & 15;
    const int r0 = ty << 2, c0 = tx << 2;
    const int qt = blockIdx.x;          // query tile index (0..31)
    const int bh = blockIdx.y;          // b*NH + h      (0..31)
    const int q0 = qt << 6;

    const float* Q = g_q + (size_t)bh * SEQ * HD;
    const float* K = g_k + (size_t)bh * SEQ * HD;
    const float* V = g_v + (size_t)bh * SEQ * HD;

    const int lr = tid >> 4;            // load row base (0..15)
    const int lc = (tid & 15) << 2;     // load col4 (0..60)

    // Load Q tile transposed, scale folded in (1/sqrt(64) = 0.125)
#pragma unroll
    for (int rep = 0; rep < 4; rep++) {
        const int r = lr + (rep << 4);
        float4 q4 = *(const float4*)&Q[(size_t)(q0 + r) * HD + lc];
        Qs[lc + 0][r] = q4.x * 0.125f;
        Qs[lc + 1][r] = q4.y * 0.125f;
        Qs[lc + 2][r] = q4.z * 0.125f;
        Qs[lc + 3][r] = q4.w * 0.125f;
    }

    float m[4], l[4], o[4][4];
#pragma unroll
    for (int i = 0; i < 4; i++) {
        m[i] = -1e30f; l[i] = 0.f;
#pragma unroll
        for (int j = 0; j < 4; j++) o[i][j] = 0.f;
    }

    for (int kt = 0; kt <= qt; kt++) {
        const int k0 = kt << 6;
        __syncthreads();   // protect Ks/Vs from previous iteration's readers
#pragma unroll
        for (int rep = 0; rep < 4; rep++) {
            const int r = lr + (rep << 4);
            float4 k4 = *(const float4*)&K[(size_t)(k0 + r) * HD + lc];
            Ks[lc + 0][r] = k4.x; Ks[lc + 1][r] = k4.y;
            Ks[lc + 2][r] = k4.z; Ks[lc + 3][r] = k4.w;
            float4 v4 = *(const float4*)&V[(size_t)(k0 + r) * HD + lc];
            *(float4*)&Vs[r][lc] = v4;
        }
        __syncthreads();

        // S = (Q*scale) @ K^T   (64x64x64)
        float s[4][4] = {};
#pragma unroll 8
        for (int d = 0; d < 64; d++) {
            float4 a = *(const float4*)&Qs[d][r0];
            float4 b = *(const float4*)&Ks[d][c0];
            float av[4] = {a.x, a.y, a.z, a.w};
            float bv[4] = {b.x, b.y, b.z, b.w};
#pragma unroll
            for (int i = 0; i < 4; i++)
#pragma unroll
                for (int j = 0; j < 4; j++)
                    s[i][j] = fmaf(av[i], bv[j], s[i][j]);
        }

        // causal mask (only the diagonal tile is partially masked)
        if (kt == qt) {
#pragma unroll
            for (int i = 0; i < 4; i++)
#pragma unroll
                for (int j = 0; j < 4; j++)
                    if (c0 + j > r0 + i) s[i][j] = -1e9f;
        }

        // row max over 64 cols: local max + xor-shfl across the 16 tx lanes
        float rm[4];
#pragma unroll
        for (int i = 0; i < 4; i++)
            rm[i] = fmaxf(fmaxf(s[i][0], s[i][1]), fmaxf(s[i][2], s[i][3]));
#pragma unroll
        for (int off = 1; off < 16; off <<= 1)
#pragma unroll
            for (int i = 0; i < 4; i++)
                rm[i] = fmaxf(rm[i], __shfl_xor_sync(0xffffffffu, rm[i], off));

        float mn[4], corr[4];
#pragma unroll
        for (int i = 0; i < 4; i++) {
            mn[i] = fmaxf(m[i], rm[i]);
            corr[i] = __expf(m[i] - mn[i]);
            m[i] = mn[i];
        }

        float rs[4];
#pragma unroll
        for (int i = 0; i < 4; i++) {
            float t0 = 0.f;
#pragma unroll
            for (int j = 0; j < 4; j++) {
                s[i][j] = __expf(s[i][j] - mn[i]);
                t0 += s[i][j];
            }
            rs[i] = t0;
        }
#pragma unroll
        for (int off = 1; off < 16; off <<= 1)
#pragma unroll
            for (int i = 0; i < 4; i++)
                rs[i] += __shfl_xor_sync(0xffffffffu, rs[i], off);

#pragma unroll
        for (int i = 0; i < 4; i++) {
            l[i] = l[i] * corr[i] + rs[i];
#pragma unroll
            for (int j = 0; j < 4; j++) o[i][j] *= corr[i];
        }

        // stash P transposed for the PV GEMM
#pragma unroll
        for (int i = 0; i < 4; i++)
#pragma unroll
            for (int j = 0; j < 4; j++)
                Ps[c0 + j][r0 + i] = s[i][j];
        __syncthreads();

        // O += P @ V   (64x64x64)
#pragma unroll 8
        for (int j = 0; j < 64; j++) {
            float4 p = *(const float4*)&Ps[j][r0];
            float4 v = *(const float4*)&Vs[j][c0];
            float pv[4] = {p.x, p.y, p.z, p.w};
            float vv[4] = {v.x, v.y, v.z, v.w};
#pragma unroll
            for (int i = 0; i < 4; i++)
#pragma unroll
                for (int u = 0; u < 4; u++)
                    o[i][u] = fmaf(pv[i], vv[u], o[i][u]);
        }
    }

    // normalize and write merged-head output [T, E]
    const int b = bh >> 4, h = bh & 15;
#pragma unroll
    for (int i = 0; i < 4; i++) {
        const size_t t = (size_t)b * SEQ + q0 + r0 + i;
        const float inv = 1.f / l[i];
#pragma unroll
        for (int j = 0; j < 4; j++)
            g_x[t * EMB + h * HD + c0 + j] = o[i][j] * inv;
    }
}

// ---------------------------------------------------------------------------
extern "C" void kernel_launch(void* const* d_in, const int* in_sizes, int n_in,
                              void* d_out, int out_size)
{
    const float* v  = (const float*)d_in[0];
    const float* k  = (const float*)d_in[1];
    const float* q  = (const float*)d_in[2];
    // d_in[3] = mask (causal, deterministic) — handled analytically in-kernel
    const float* wq = (const float*)d_in[4];
    const float* bq = (const float*)d_in[5];
    const float* wk = (const float*)d_in[6];
    const float* bk = (const float*)d_in[7];
    const float* wv = (const float*)d_in[8];
    const float* bv = (const float*)d_in[9];
    const float* wo = (const float*)d_in[10];
    const float* bo = (const float*)d_in[11];
    float* out = (float*)d_out;

    dim3 blk(256);
    dim3 gg(EMB / 64, TOK / 64);

    gemm64<0, false><<<gg, blk>>>(q, wq, bq, nullptr);
    gemm64<1, false><<<gg, blk>>>(k, wk, bk, nullptr);
    gemm64<2, false><<<gg, blk>>>(v, wv, bv, nullptr);

    const size_t attn_smem = 4 * 64 * 68 * sizeof(float);  // 69632 B
    cudaFuncSetAttribute(attn_kernel, cudaFuncAttributeMaxDynamicSharedMemorySize,
                         (int)attn_smem);
    attn_kernel<<<dim3(SEQ / 64, BSZ * NH), blk, attn_smem>>>();

    gemm64<3, true><<<gg, blk>>>(nullptr, wo, bo, out);
}

// round 3
// speedup vs baseline: 1.3933x; 1.3933x over previous
#include <cuda_runtime.h>
#include <cuda_bf16.h>
#include <stdint.h>
#include <math.h>

#define TOK 4096     // B*S
#define EMB 1024     // E
#define SEQ 2048     // S
#define BSZ 2        // B
#define NH  16       // heads
#define HD  64       // head dim

// Scratch (device globals — allocation-free per harness rules)
__device__ float g_q[(size_t)TOK * EMB];  // [B,H,S,D]
__device__ float g_k[(size_t)TOK * EMB];  // [B,H,S,D]
__device__ float g_v[(size_t)TOK * EMB];  // [B,H,S,D]
__device__ float g_x[(size_t)TOK * EMB];  // [T,E] attention output (heads merged)
__device__ __nv_bfloat16 g_wthi[(size_t)EMB * EMB];  // W^T hi  [N,K] K-major
__device__ __nv_bfloat16 g_wtlo[(size_t)EMB * EMB];  // W^T lo

// ===========================================================================
// Family-safe PTX helpers (no tcgen05 — ptxas target is compute_103 family)
// ===========================================================================
__device__ __forceinline__ uint32_t smem_u32(const void* p) {
    uint32_t a;
    asm("{ .reg .u64 t; cvta.to.shared.u64 t, %1; cvt.u32.u64 %0, t; }"
        : "=r"(a) : "l"(p));
    return a;
}
__device__ __forceinline__ void ldsm4(uint32_t* r, uint32_t addr) {
    asm volatile("ldmatrix.sync.aligned.m8n8.x4.shared.b16 {%0,%1,%2,%3}, [%4];"
        : "=r"(r[0]), "=r"(r[1]), "=r"(r[2]), "=r"(r[3]) : "r"(addr));
}
__device__ __forceinline__ void mma16816(float* c, const uint32_t* a, const uint32_t* b) {
    asm volatile("mma.sync.aligned.m16n8k16.row.col.f32.bf16.bf16.f32 "
        "{%0,%1,%2,%3}, {%4,%5,%6,%7}, {%8,%9}, {%0,%1,%2,%3};"
        : "+f"(c[0]), "+f"(c[1]), "+f"(c[2]), "+f"(c[3])
        : "r"(a[0]), "r"(a[1]), "r"(a[2]), "r"(a[3]), "r"(b[0]), "r"(b[1]));
}
__device__ __forceinline__ void cp16(uint32_t dst, const void* src) {
    asm volatile("cp.async.cg.shared.global [%0], [%1], 16;" :: "r"(dst), "l"(src));
}
#define CP_COMMIT() asm volatile("cp.async.commit_group;" ::: "memory")
#define CP_WAIT0()  asm volatile("cp.async.wait_group 0;" ::: "memory")

// ===========================================================================
// W^T split-precision transpose: W[k][n] fp32 -> g_wthi/lo[n][k] bf16
// ===========================================================================
__global__ __launch_bounds__(256)
void wtrans(const float* __restrict__ W)
{
    __shared__ float t[32][33];
    const int tx = threadIdx.x, ty = threadIdx.y;
    const int x = blockIdx.x * 32 + tx;
#pragma unroll
    for (int j = 0; j < 4; j++)
        t[ty + 8 * j][tx] = W[(size_t)(blockIdx.y * 32 + ty + 8 * j) * EMB + x];
    __syncthreads();
    const int x2 = blockIdx.y * 32 + tx;
#pragma unroll
    for (int j = 0; j < 4; j++) {
        const float f = t[tx][ty + 8 * j];
        const __nv_bfloat16 hi = __float2bfloat16_rn(f);
        const __nv_bfloat16 lo = __float2bfloat16_rn(f - __bfloat162float(hi));
        const size_t idx = (size_t)(blockIdx.x * 32 + ty + 8 * j) * EMB + x2;
        g_wthi[idx] = hi;
        g_wtlo[idx] = lo;
    }
}

// ===========================================================================
// HMMA GEMM: C[4096,1024] = A @ W + bias  via bf16x3 (hihi + hilo + lohi)
// 128x128 CTA tile, BK=32, 8 warps (4x2), warp tile 32x64, double-buffered.
// DST 0/1/2 -> g_q/g_k/g_v head-split; 3 -> Cout row-major. SRC_GX: A = g_x.
// ===========================================================================
#define ROWB 80                       // padded row bytes (40 bf16)
#define ASZ  (128 * ROWB)             // 10240 bytes per operand plane
#define STG  (4 * ASZ)                // Ahi|Alo|Bhi|Blo per stage
#define GEMM_SMEM (2 * STG)           // 81920 bytes

template<int DST, bool SRC_GX>
__global__ __launch_bounds__(256)
void gemm_tc(const float* __restrict__ Ain, const float* __restrict__ bias,
             float* __restrict__ Cout)
{
    extern __shared__ char smem[];
    const uint32_t sbase = smem_u32(smem);
    const float* A = SRC_GX ? g_x : Ain;

    const int tid = threadIdx.x;
    const int lane = tid & 31;
    const int wm = (tid >> 5) >> 1;     // 0..3
    const int wn = (tid >> 5) & 1;      // 0..1
    const int m0 = blockIdx.y << 7, n0 = blockIdx.x << 7;

    // ldmatrix lane offsets (bytes, within operand plane; add mi*1280 / g*1280, ks*32)
    const uint32_t aoff = (uint32_t)(wm * 32 + (lane & 7) + ((lane >> 3) & 1) * 8) * ROWB
                        + ((lane >> 4) & 1) * 16;
    const uint32_t boff = (uint32_t)(wn * 64 + (lane & 7) + ((lane >> 4) & 1) * 8) * ROWB
                        + ((lane >> 3) & 1) * 16;

    // staging coords
    const int row = tid >> 1;           // 0..127
    const int half = tid & 1;           // 0/1

    const float* aG = A + (size_t)(m0 + row) * EMB + half * 16;
    const __nv_bfloat16* bhG = g_wthi + (size_t)(n0 + row) * EMB + half * 16;
    const __nv_bfloat16* blG = g_wtlo + (size_t)(n0 + row) * EMB + half * 16;
    const uint32_t stsA = (uint32_t)row * ROWB + half * 32;
    const uint32_t stsB = stsA;

    float c[2][8][4];
#pragma unroll
    for (int i = 0; i < 2; i++)
#pragma unroll
        for (int j = 0; j < 8; j++)
#pragma unroll
            for (int u = 0; u < 4; u++) c[i][j][u] = 0.f;

    float4 aR[4];

    // ---- prologue: chunk 0 into stage 0 ----
    {
        const uint32_t st = sbase;
#pragma unroll
        for (int j = 0; j < 2; j++) {
            cp16(st + 2 * ASZ + stsB + 16 * j, bhG + 8 * j);
            cp16(st + 3 * ASZ + stsB + 16 * j, blG + 8 * j);
        }
        CP_COMMIT();
#pragma unroll
        for (int i = 0; i < 4; i++) aR[i] = *(const float4*)(aG + 4 * i);
#pragma unroll
        for (int i = 0; i < 4; i++) {
            const float4 a = aR[i];
            const __nv_bfloat16 h0 = __float2bfloat16_rn(a.x);
            const __nv_bfloat16 h1 = __float2bfloat16_rn(a.y);
            const __nv_bfloat16 h2 = __float2bfloat16_rn(a.z);
            const __nv_bfloat16 h3 = __float2bfloat16_rn(a.w);
            uint2 uh, ul;
            uh.x = ((uint32_t)__bfloat16_as_ushort(h1) << 16) | __bfloat16_as_ushort(h0);
            uh.y = ((uint32_t)__bfloat16_as_ushort(h3) << 16) | __bfloat16_as_ushort(h2);
            ul.x = ((uint32_t)__bfloat16_as_ushort(__float2bfloat16_rn(a.y - __bfloat162float(h1))) << 16)
                 |  __bfloat16_as_ushort(__float2bfloat16_rn(a.x - __bfloat162float(h0)));
            ul.y = ((uint32_t)__bfloat16_as_ushort(__float2bfloat16_rn(a.w - __bfloat162float(h3))) << 16)
                 |  __bfloat16_as_ushort(__float2bfloat16_rn(a.z - __bfloat162float(h2)));
            *(uint2*)(smem + stsA + 8 * i) = uh;
            *(uint2*)(smem + ASZ + stsA + 8 * i) = ul;
        }
        CP_WAIT0();
        __syncthreads();
    }

    const int NCH = EMB / 32;  // 32 chunks
    for (int ck = 0; ck < NCH; ck++) {
        const uint32_t cbs = sbase + (uint32_t)(ck & 1) * STG;        // compute stage
        const uint32_t nbs = sbase + (uint32_t)((ck + 1) & 1) * STG;  // next stage
        const int koff = (ck + 1) * 32;

        // issue next chunk's B cp.async + A global loads (overlap with MMA)
        if (ck + 1 < NCH) {
#pragma unroll
            for (int j = 0; j < 2; j++) {
                cp16(nbs + 2 * ASZ + stsB + 16 * j, bhG + koff + 8 * j);
                cp16(nbs + 3 * ASZ + stsB + 16 * j, blG + koff + 8 * j);
            }
            CP_COMMIT();
#pragma unroll
            for (int i = 0; i < 4; i++)
                aR[i] = *(const float4*)(aG + koff + 4 * i);
        }

        // ---- MMA on compute stage ----
#pragma unroll
        for (int ks = 0; ks < 2; ks++) {
            uint32_t ahi[2][4], alo[2][4];
            ldsm4(ahi[0], cbs + aoff + ks * 32);
            ldsm4(ahi[1], cbs + aoff + 1280 + ks * 32);
            ldsm4(alo[0], cbs + ASZ + aoff + ks * 32);
            ldsm4(alo[1], cbs + ASZ + aoff + 1280 + ks * 32);
            uint32_t bhi[4][4], blo[4][4];
#pragma unroll
            for (int g = 0; g < 4; g++) {
                ldsm4(bhi[g], cbs + 2 * ASZ + boff + g * 1280 + ks * 32);
                ldsm4(blo[g], cbs + 3 * ASZ + boff + g * 1280 + ks * 32);
            }
#pragma unroll
            for (int mi = 0; mi < 2; mi++)
#pragma unroll
                for (int g = 0; g < 4; g++) {
                    mma16816(c[mi][2 * g],     ahi[mi], &bhi[g][0]);
                    mma16816(c[mi][2 * g],     ahi[mi], &blo[g][0]);
                    mma16816(c[mi][2 * g],     alo[mi], &bhi[g][0]);
                    mma16816(c[mi][2 * g + 1], ahi[mi], &bhi[g][2]);
                    mma16816(c[mi][2 * g + 1], ahi[mi], &blo[g][2]);
                    mma16816(c[mi][2 * g + 1], alo[mi], &bhi[g][2]);
                }
        }

        // ---- stage next A chunk ----
        if (ck + 1 < NCH) {
#pragma unroll
            for (int i = 0; i < 4; i++) {
                const float4 a = aR[i];
                const __nv_bfloat16 h0 = __float2bfloat16_rn(a.x);
                const __nv_bfloat16 h1 = __float2bfloat16_rn(a.y);
                const __nv_bfloat16 h2 = __float2bfloat16_rn(a.z);
                const __nv_bfloat16 h3 = __float2bfloat16_rn(a.w);
                uint2 uh, ul;
                uh.x = ((uint32_t)__bfloat16_as_ushort(h1) << 16) | __bfloat16_as_ushort(h0);
                uh.y = ((uint32_t)__bfloat16_as_ushort(h3) << 16) | __bfloat16_as_ushort(h2);
                ul.x = ((uint32_t)__bfloat16_as_ushort(__float2bfloat16_rn(a.y - __bfloat162float(h1))) << 16)
                     |  __bfloat16_as_ushort(__float2bfloat16_rn(a.x - __bfloat162float(h0)));
                ul.y = ((uint32_t)__bfloat16_as_ushort(__float2bfloat16_rn(a.w - __bfloat162float(h3))) << 16)
                     |  __bfloat16_as_ushort(__float2bfloat16_rn(a.z - __bfloat162float(h2)));
                const uint32_t off = (uint32_t)((ck + 1) & 1) * STG + stsA + 8 * i;
                *(uint2*)(smem + off) = uh;
                *(uint2*)(smem + ASZ + off) = ul;
            }
        }
        CP_WAIT0();
        __syncthreads();
    }

    // ---- epilogue: fragments -> gmem with bias ----
#pragma unroll
    for (int mi = 0; mi < 2; mi++) {
        const int mr = m0 + wm * 32 + mi * 16 + (lane >> 2);
#pragma unroll
        for (int nf = 0; nf < 8; nf++) {
            const int nc = n0 + wn * 64 + nf * 8 + (lane & 3) * 2;
#pragma unroll
            for (int u = 0; u < 4; u++) {
                const int m = mr + (u >> 1) * 8;      // regs 2,3 -> +8 rows
                const int n = nc + (u & 1);
                const float val = c[mi][nf][u] + __ldg(&bias[n]);
                if (DST <= 2) {
                    float* C = (DST == 0) ? g_q : (DST == 1) ? g_k : g_v;
                    const int b = m >> 11, s = m & (SEQ - 1);
                    const int h = n >> 6,  d = n & (HD - 1);
                    C[(((size_t)b * NH + h) * SEQ + s) * HD + d] = val;
                } else {
                    Cout[(size_t)m * EMB + n] = val;
                }
            }
        }
    }
}

// ---------------------------------------------------------------------------
// Causal flash attention, fp32 (unchanged — tensor port is next round)
// ---------------------------------------------------------------------------
__global__ __launch_bounds__(256)
void attn_kernel()
{
    extern __shared__ float sm[];
    float (*Qs)[68] = (float(*)[68])(sm);
    float (*Ks)[68] = (float(*)[68])(sm + 64 * 68);
    float (*Vs)[68] = (float(*)[68])(sm + 2 * 64 * 68);
    float (*Ps)[68] = (float(*)[68])(sm + 3 * 64 * 68);

    const int tid = threadIdx.x;
    const int ty = tid >> 4, tx = tid & 15;
    const int r0 = ty << 2, c0 = tx << 2;
    const int qt = blockIdx.x;
    const int bh = blockIdx.y;
    const int q0 = qt << 6;

    const float* Q = g_q + (size_t)bh * SEQ * HD;
    const float* K = g_k + (size_t)bh * SEQ * HD;
    const float* V = g_v + (size_t)bh * SEQ * HD;

    const int lr = tid >> 4;
    const int lc = (tid & 15) << 2;

#pragma unroll
    for (int rep = 0; rep < 4; rep++) {
        const int r = lr + (rep << 4);
        float4 q4 = *(const float4*)&Q[(size_t)(q0 + r) * HD + lc];
        Qs[lc + 0][r] = q4.x * 0.125f;
        Qs[lc + 1][r] = q4.y * 0.125f;
        Qs[lc + 2][r] = q4.z * 0.125f;
        Qs[lc + 3][r] = q4.w * 0.125f;
    }

    float m[4], l[4], o[4][4];
#pragma unroll
    for (int i = 0; i < 4; i++) {
        m[i] = -1e30f; l[i] = 0.f;
#pragma unroll
        for (int j = 0; j < 4; j++) o[i][j] = 0.f;
    }

    for (int kt = 0; kt <= qt; kt++) {
        const int k0 = kt << 6;
        __syncthreads();
#pragma unroll
        for (int rep = 0; rep < 4; rep++) {
            const int r = lr + (rep << 4);
            float4 k4 = *(const float4*)&K[(size_t)(k0 + r) * HD + lc];
            Ks[lc + 0][r] = k4.x; Ks[lc + 1][r] = k4.y;
            Ks[lc + 2][r] = k4.z; Ks[lc + 3][r] = k4.w;
            float4 v4 = *(const float4*)&V[(size_t)(k0 + r) * HD + lc];
            *(float4*)&Vs[r][lc] = v4;
        }
        __syncthreads();

        float s[4][4] = {};
#pragma unroll 8
        for (int d = 0; d < 64; d++) {
            float4 a = *(const float4*)&Qs[d][r0];
            float4 b = *(const float4*)&Ks[d][c0];
            float av[4] = {a.x, a.y, a.z, a.w};
            float bv[4] = {b.x, b.y, b.z, b.w};
#pragma unroll
            for (int i = 0; i < 4; i++)
#pragma unroll
                for (int j = 0; j < 4; j++)
                    s[i][j] = fmaf(av[i], bv[j], s[i][j]);
        }

        if (kt == qt) {
#pragma unroll
            for (int i = 0; i < 4; i++)
#pragma unroll
                for (int j = 0; j < 4; j++)
                    if (c0 + j > r0 + i) s[i][j] = -1e9f;
        }

        float rm[4];
#pragma unroll
        for (int i = 0; i < 4; i++)
            rm[i] = fmaxf(fmaxf(s[i][0], s[i][1]), fmaxf(s[i][2], s[i][3]));
#pragma unroll
        for (int off = 1; off < 16; off <<= 1)
#pragma unroll
            for (int i = 0; i < 4; i++)
                rm[i] = fmaxf(rm[i], __shfl_xor_sync(0xffffffffu, rm[i], off));

        float mn[4], corr[4];
#pragma unroll
        for (int i = 0; i < 4; i++) {
            mn[i] = fmaxf(m[i], rm[i]);
            corr[i] = __expf(m[i] - mn[i]);
            m[i] = mn[i];
        }

        float rs[4];
#pragma unroll
        for (int i = 0; i < 4; i++) {
            float t0 = 0.f;
#pragma unroll
            for (int j = 0; j < 4; j++) {
                s[i][j] = __expf(s[i][j] - mn[i]);
                t0 += s[i][j];
            }
            rs[i] = t0;
        }
#pragma unroll
        for (int off = 1; off < 16; off <<= 1)
#pragma unroll
            for (int i = 0; i < 4; i++)
                rs[i] += __shfl_xor_sync(0xffffffffu, rs[i], off);

#pragma unroll
        for (int i = 0; i < 4; i++) {
            l[i] = l[i] * corr[i] + rs[i];
#pragma unroll
            for (int j = 0; j < 4; j++) o[i][j] *= corr[i];
        }

#pragma unroll
        for (int i = 0; i < 4; i++)
#pragma unroll
            for (int j = 0; j < 4; j++)
                Ps[c0 + j][r0 + i] = s[i][j];
        __syncthreads();

#pragma unroll 8
        for (int j = 0; j < 64; j++) {
            float4 p = *(const float4*)&Ps[j][r0];
            float4 v = *(const float4*)&Vs[j][c0];
            float pv[4] = {p.x, p.y, p.z, p.w};
            float vv[4] = {v.x, v.y, v.z, v.w};
#pragma unroll
            for (int i = 0; i < 4; i++)
#pragma unroll
                for (int u = 0; u < 4; u++)
                    o[i][u] = fmaf(pv[i], vv[u], o[i][u]);
        }
    }

    const int b = bh >> 4, h = bh & 15;
#pragma unroll
    for (int i = 0; i < 4; i++) {
        const size_t t = (size_t)b * SEQ + q0 + r0 + i;
        const float inv = 1.f / l[i];
#pragma unroll
        for (int j = 0; j < 4; j++)
            g_x[t * EMB + h * HD + c0 + j] = o[i][j] * inv;
    }
}

// ---------------------------------------------------------------------------
extern "C" void kernel_launch(void* const* d_in, const int* in_sizes, int n_in,
                              void* d_out, int out_size)
{
    const float* v  = (const float*)d_in[0];
    const float* k  = (const float*)d_in[1];
    const float* q  = (const float*)d_in[2];
    const float* wq = (const float*)d_in[4];
    const float* bq = (const float*)d_in[5];
    const float* wk = (const float*)d_in[6];
    const float* bk = (const float*)d_in[7];
    const float* wv = (const float*)d_in[8];
    const float* bv = (const float*)d_in[9];
    const float* wo = (const float*)d_in[10];
    const float* bo = (const float*)d_in[11];
    float* out = (float*)d_out;

    cudaFuncSetAttribute(gemm_tc<0, false>, cudaFuncAttributeMaxDynamicSharedMemorySize, GEMM_SMEM);
    cudaFuncSetAttribute(gemm_tc<1, false>, cudaFuncAttributeMaxDynamicSharedMemorySize, GEMM_SMEM);
    cudaFuncSetAttribute(gemm_tc<2, false>, cudaFuncAttributeMaxDynamicSharedMemorySize, GEMM_SMEM);
    cudaFuncSetAttribute(gemm_tc<3, true>,  cudaFuncAttributeMaxDynamicSharedMemorySize, GEMM_SMEM);

    const dim3 tblk(32, 8);
    const dim3 tgrd(EMB / 32, EMB / 32);
    const dim3 gblk(256);
    const dim3 ggrd(EMB / 128, TOK / 128);

    wtrans<<<tgrd, tblk>>>(wq);
    gemm_tc<0, false><<<ggrd, gblk, GEMM_SMEM>>>(q, bq, nullptr);
    wtrans<<<tgrd, tblk>>>(wk);
    gemm_tc<1, false><<<ggrd, gblk, GEMM_SMEM>>>(k, bk, nullptr);
    wtrans<<<tgrd, tblk>>>(wv);
    gemm_tc<2, false><<<ggrd, gblk, GEMM_SMEM>>>(v, bv, nullptr);

    const size_t attn_smem = 4 * 64 * 68 * sizeof(float);
    cudaFuncSetAttribute(attn_kernel, cudaFuncAttributeMaxDynamicSharedMemorySize,
                         (int)attn_smem);
    attn_kernel<<<dim3(SEQ / 64, BSZ * NH), gblk, attn_smem>>>();

    wtrans<<<tgrd, tblk>>>(wo);
    gemm_tc<3, true><<<ggrd, gblk, GEMM_SMEM>>>(nullptr, bo, out);
}

// round 4
// speedup vs baseline: 2.2853x; 1.6402x over previous
#include <cuda_runtime.h>
#include <cuda_bf16.h>
#include <stdint.h>
#include <math.h>

#define TOK 4096     // B*S
#define EMB 1024     // E
#define SEQ 2048     // S
#define BSZ 2        // B
#define NH  16       // heads
#define HD  64       // head dim

// Scratch (device globals — allocation-free per harness rules)
__device__ float g_x[(size_t)TOK * EMB];             // attention output [T,E]
__device__ __nv_bfloat16 g_wthi[(size_t)EMB * EMB];  // W^T hi [N,K]
__device__ __nv_bfloat16 g_wtlo[(size_t)EMB * EMB];  // W^T lo
__device__ __nv_bfloat16 g_qh[(size_t)TOK * EMB];    // Q hi [B,H,S,D] (pre-scaled)
__device__ __nv_bfloat16 g_ql[(size_t)TOK * EMB];
__device__ __nv_bfloat16 g_kh[(size_t)TOK * EMB];
__device__ __nv_bfloat16 g_kl[(size_t)TOK * EMB];
__device__ __nv_bfloat16 g_vh[(size_t)TOK * EMB];
__device__ __nv_bfloat16 g_vl[(size_t)TOK * EMB];

// ===========================================================================
// Family-safe PTX helpers (no tcgen05 — ptxas target is compute_103 family)
// ===========================================================================
__device__ __forceinline__ uint32_t smem_u32(const void* p) {
    uint32_t a;
    asm("{ .reg .u64 t; cvta.to.shared.u64 t, %1; cvt.u32.u64 %0, t; }"
        : "=r"(a) : "l"(p));
    return a;
}
__device__ __forceinline__ void ldsm4(uint32_t* r, uint32_t addr) {
    asm volatile("ldmatrix.sync.aligned.m8n8.x4.shared.b16 {%0,%1,%2,%3}, [%4];"
        : "=r"(r[0]), "=r"(r[1]), "=r"(r[2]), "=r"(r[3]) : "r"(addr));
}
__device__ __forceinline__ void ldsm4t(uint32_t* r, uint32_t addr) {
    asm volatile("ldmatrix.sync.aligned.m8n8.x4.trans.shared.b16 {%0,%1,%2,%3}, [%4];"
        : "=r"(r[0]), "=r"(r[1]), "=r"(r[2]), "=r"(r[3]) : "r"(addr));
}
__device__ __forceinline__ void mma16816(float* c, const uint32_t* a, const uint32_t* b) {
    asm volatile("mma.sync.aligned.m16n8k16.row.col.f32.bf16.bf16.f32 "
        "{%0,%1,%2,%3}, {%4,%5,%6,%7}, {%8,%9}, {%0,%1,%2,%3};"
        : "+f"(c[0]), "+f"(c[1]), "+f"(c[2]), "+f"(c[3])
        : "r"(a[0]), "r"(a[1]), "r"(a[2]), "r"(a[3]), "r"(b[0]), "r"(b[1]));
}
__device__ __forceinline__ void cp16(uint32_t dst, const void* src) {
    asm volatile("cp.async.cg.shared.global [%0], [%1], 16;" :: "r"(dst), "l"(src));
}
#define CP_COMMIT() asm volatile("cp.async.commit_group;" ::: "memory")
#define CP_WAIT0()  asm volatile("cp.async.wait_group 0;" ::: "memory")
#define CP_WAIT1()  asm volatile("cp.async.wait_group 1;" ::: "memory")

// split fp32 pair -> packed bf16 hi plane + lo plane (x low half, y high half)
__device__ __forceinline__ void split2(float x, float y, uint32_t& hi, uint32_t& lo) {
    const __nv_bfloat16 hx = __float2bfloat16_rn(x), hy = __float2bfloat16_rn(y);
    hi = ((uint32_t)__bfloat16_as_ushort(hy) << 16) | __bfloat16_as_ushort(hx);
    const __nv_bfloat16 lx = __float2bfloat16_rn(x - __bfloat162float(hx));
    const __nv_bfloat16 ly = __float2bfloat16_rn(y - __bfloat162float(hy));
    lo = ((uint32_t)__bfloat16_as_ushort(ly) << 16) | __bfloat16_as_ushort(lx);
}

// ===========================================================================
// W^T split-precision transpose: W[k][n] fp32 -> g_wthi/lo[n][k] bf16
// ===========================================================================
__global__ __launch_bounds__(256)
void wtrans(const float* __restrict__ W)
{
    __shared__ float t[32][33];
    const int tx = threadIdx.x, ty = threadIdx.y;
    const int x = blockIdx.x * 32 + tx;
#pragma unroll
    for (int j = 0; j < 4; j++)
        t[ty + 8 * j][tx] = W[(size_t)(blockIdx.y * 32 + ty + 8 * j) * EMB + x];
    __syncthreads();
    const int x2 = blockIdx.y * 32 + tx;
#pragma unroll
    for (int j = 0; j < 4; j++) {
        const float f = t[tx][ty + 8 * j];
        const __nv_bfloat16 hi = __float2bfloat16_rn(f);
        const __nv_bfloat16 lo = __float2bfloat16_rn(f - __bfloat162float(hi));
        const size_t idx = (size_t)(blockIdx.x * 32 + ty + 8 * j) * EMB + x2;
        g_wthi[idx] = hi;
        g_wtlo[idx] = lo;
    }
}

// ===========================================================================
// HMMA GEMM: C = A @ W + bias via bf16x3. 128x128 tile, BK=32, 8 warps.
// DST 0/1/2 -> bf16 hi/lo planes (q scaled by 0.125), head-split layout.
// DST 3 -> fp32 Cout row-major. SRC_GX: A = g_x.
// ===========================================================================
#define ROWB 80
#define ASZ  (128 * ROWB)
#define STG  (4 * ASZ)
#define GEMM_SMEM (2 * STG)

template<int DST, bool SRC_GX>
__global__ __launch_bounds__(256)
void gemm_tc(const float* __restrict__ Ain, const float* __restrict__ bias,
             float* __restrict__ Cout)
{
    extern __shared__ char smem[];
    const uint32_t sbase = smem_u32(smem);
    const float* A = SRC_GX ? g_x : Ain;

    const int tid = threadIdx.x;
    const int lane = tid & 31;
    const int wm = (tid >> 5) >> 1;
    const int wn = (tid >> 5) & 1;
    const int m0 = blockIdx.y << 7, n0 = blockIdx.x << 7;

    const uint32_t aoff = (uint32_t)(wm * 32 + (lane & 7) + ((lane >> 3) & 1) * 8) * ROWB
                        + ((lane >> 4) & 1) * 16;
    const uint32_t boff = (uint32_t)(wn * 64 + (lane & 7) + ((lane >> 4) & 1) * 8) * ROWB
                        + ((lane >> 3) & 1) * 16;

    const int row = tid >> 1;
    const int half = tid & 1;

    const float* aG = A + (size_t)(m0 + row) * EMB + half * 16;
    const __nv_bfloat16* bhG = g_wthi + (size_t)(n0 + row) * EMB + half * 16;
    const __nv_bfloat16* blG = g_wtlo + (size_t)(n0 + row) * EMB + half * 16;
    const uint32_t stsA = (uint32_t)row * ROWB + half * 32;

    float c[2][8][4];
#pragma unroll
    for (int i = 0; i < 2; i++)
#pragma unroll
        for (int j = 0; j < 8; j++)
#pragma unroll
            for (int u = 0; u < 4; u++) c[i][j][u] = 0.f;

    float4 aR[4];

    // prologue
    {
#pragma unroll
        for (int j = 0; j < 2; j++) {
            cp16(sbase + 2 * ASZ + stsA + 16 * j, bhG + 8 * j);
            cp16(sbase + 3 * ASZ + stsA + 16 * j, blG + 8 * j);
        }
        CP_COMMIT();
#pragma unroll
        for (int i = 0; i < 4; i++) aR[i] = *(const float4*)(aG + 4 * i);
#pragma unroll
        for (int i = 0; i < 4; i++) {
            uint2 uh, ul;
            split2(aR[i].x, aR[i].y, uh.x, ul.x);
            split2(aR[i].z, aR[i].w, uh.y, ul.y);
            *(uint2*)(smem + stsA + 8 * i) = uh;
            *(uint2*)(smem + ASZ + stsA + 8 * i) = ul;
        }
        CP_WAIT0();
        __syncthreads();
    }

    const int NCH = EMB / 32;
    for (int ck = 0; ck < NCH; ck++) {
        const uint32_t cbs = sbase + (uint32_t)(ck & 1) * STG;
        const uint32_t nbs = sbase + (uint32_t)((ck + 1) & 1) * STG;
        const int koff = (ck + 1) * 32;

        if (ck + 1 < NCH) {
#pragma unroll
            for (int j = 0; j < 2; j++) {
                cp16(nbs + 2 * ASZ + stsA + 16 * j, bhG + koff + 8 * j);
                cp16(nbs + 3 * ASZ + stsA + 16 * j, blG + koff + 8 * j);
            }
            CP_COMMIT();
#pragma unroll
            for (int i = 0; i < 4; i++)
                aR[i] = *(const float4*)(aG + koff + 4 * i);
        }

#pragma unroll
        for (int ks = 0; ks < 2; ks++) {
            uint32_t ahi[2][4], alo[2][4];
            ldsm4(ahi[0], cbs + aoff + ks * 32);
            ldsm4(ahi[1], cbs + aoff + 1280 + ks * 32);
            ldsm4(alo[0], cbs + ASZ + aoff + ks * 32);
            ldsm4(alo[1], cbs + ASZ + aoff + 1280 + ks * 32);
            uint32_t bhi[4][4], blo[4][4];
#pragma unroll
            for (int g = 0; g < 4; g++) {
                ldsm4(bhi[g], cbs + 2 * ASZ + boff + g * 1280 + ks * 32);
                ldsm4(blo[g], cbs + 3 * ASZ + boff + g * 1280 + ks * 32);
            }
#pragma unroll
            for (int mi = 0; mi < 2; mi++)
#pragma unroll
                for (int g = 0; g < 4; g++) {
                    mma16816(c[mi][2 * g],     ahi[mi], &bhi[g][0]);
                    mma16816(c[mi][2 * g],     ahi[mi], &blo[g][0]);
                    mma16816(c[mi][2 * g],     alo[mi], &bhi[g][0]);
                    mma16816(c[mi][2 * g + 1], ahi[mi], &bhi[g][2]);
                    mma16816(c[mi][2 * g + 1], ahi[mi], &blo[g][2]);
                    mma16816(c[mi][2 * g + 1], alo[mi], &bhi[g][2]);
                }
        }

        if (ck + 1 < NCH) {
#pragma unroll
            for (int i = 0; i < 4; i++) {
                uint2 uh, ul;
                split2(aR[i].x, aR[i].y, uh.x, ul.x);
                split2(aR[i].z, aR[i].w, uh.y, ul.y);
                const uint32_t off = (uint32_t)((ck + 1) & 1) * STG + stsA + 8 * i;
                *(uint2*)(smem + off) = uh;
                *(uint2*)(smem + ASZ + off) = ul;
            }
        }
        CP_WAIT0();
        __syncthreads();
    }

    // epilogue
#pragma unroll
    for (int mi = 0; mi < 2; mi++) {
#pragma unroll
        for (int nf = 0; nf < 8; nf++) {
            const int n = n0 + wn * 64 + nf * 8 + (lane & 3) * 2;
            const float b0 = __ldg(&bias[n]), b1 = __ldg(&bias[n + 1]);
#pragma unroll
            for (int u2 = 0; u2 < 2; u2++) {
                const int m = m0 + wm * 32 + mi * 16 + (lane >> 2) + u2 * 8;
                float v0 = c[mi][nf][2 * u2]     + b0;
                float v1 = c[mi][nf][2 * u2 + 1] + b1;
                if (DST == 0) { v0 *= 0.125f; v1 *= 0.125f; }
                if (DST <= 2) {
                    __nv_bfloat16* Ch = (DST == 0) ? g_qh : (DST == 1) ? g_kh : g_vh;
                    __nv_bfloat16* Cl = (DST == 0) ? g_ql : (DST == 1) ? g_kl : g_vl;
                    uint32_t hi, lo;
                    split2(v0, v1, hi, lo);
                    const int b = m >> 11, s = m & (SEQ - 1);
                    const int h = n >> 6,  d = n & (HD - 1);
                    const size_t idx = (((size_t)b * NH + h) * SEQ + s) * HD + d;
                    *(uint32_t*)&Ch[idx] = hi;
                    *(uint32_t*)&Cl[idx] = lo;
                } else {
                    Cout[(size_t)m * EMB + n]     = v0;
                    Cout[(size_t)m * EMB + n + 1] = v1;
                }
            }
        }
    }
}

// ===========================================================================
// Causal flash attention, HMMA bf16x3. CTA: 128 q-rows x 64-key tiles,
// 8 warps x 16 rows. Q frags register-resident; K ldsm, V ldsm.trans;
// P split hi/lo in registers (C-frag pair == A-frag). KV double-buffered.
// ===========================================================================
#define PITCH 144
#define QPL (128 * PITCH)          // 18432
#define KPL (64 * PITCH)           // 9216
#define SM_KV (2 * QPL)            // Q hi | Q lo | KV stage0 | KV stage1
#define KVSTG (4 * KPL)            // Khi | Klo | Vhi | Vlo
#define ATTN_SMEM (SM_KV + 2 * KVSTG)   // 110592

__device__ __forceinline__ void issue_kv(uint32_t stg,
    const __nv_bfloat16* KH, const __nv_bfloat16* KL,
    const __nv_bfloat16* VH, const __nv_bfloat16* VL, int k0, int tid)
{
    const int r = tid >> 2, qd = tid & 3;
    const size_t srow = (size_t)(k0 + r) * HD + qd * 16;
    const uint32_t drow = (uint32_t)r * PITCH + qd * 32;
    cp16(stg + drow,                KH + srow);
    cp16(stg + drow + 16,           KH + srow + 8);
    cp16(stg + KPL + drow,          KL + srow);
    cp16(stg + KPL + drow + 16,     KL + srow + 8);
    cp16(stg + 2 * KPL + drow,      VH + srow);
    cp16(stg + 2 * KPL + drow + 16, VH + srow + 8);
    cp16(stg + 3 * KPL + drow,      VL + srow);
    cp16(stg + 3 * KPL + drow + 16, VL + srow + 8);
}

__global__ __launch_bounds__(256)
void attn_tc()
{
    extern __shared__ char smem[];
    const uint32_t sb = smem_u32(smem);
    const int tid = threadIdx.x;
    const int lane = tid & 31, w = tid >> 5;
    const int qt = blockIdx.x, bh = blockIdx.y;
    const int q0 = qt << 7;
    const size_t base = (size_t)bh * SEQ * HD;

    const __nv_bfloat16* KH = g_kh + base;
    const __nv_bfloat16* KL = g_kl + base;
    const __nv_bfloat16* VH = g_vh + base;
    const __nv_bfloat16* VL = g_vl + base;

    // stage Q (both planes) + KV tile 0, one cp.async group
    {
        const int r = tid >> 1, hf = tid & 1;
        const __nv_bfloat16* sh = g_qh + base + (size_t)(q0 + r) * HD + hf * 32;
        const __nv_bfloat16* sl = g_ql + base + (size_t)(q0 + r) * HD + hf * 32;
        const uint32_t dh = sb + (uint32_t)r * PITCH + hf * 64;
#pragma unroll
        for (int j = 0; j < 4; j++) {
            cp16(dh + 16 * j, sh + 8 * j);
            cp16(dh + QPL + 16 * j, sl + 8 * j);
        }
        issue_kv(sb + SM_KV, KH, KL, VH, VL, 0, tid);
        CP_COMMIT();
    }

    // ldsm lane offsets
    const uint32_t aoffQ = (uint32_t)(w * 16 + (lane & 15)) * PITCH
                         + ((lane >> 4) & 1) * 16;
    const uint32_t boff = (uint32_t)((lane & 7) + ((lane >> 4) & 1) * 8) * PITCH
                        + ((lane >> 3) & 1) * 16;
    const uint32_t voff = (uint32_t)((lane & 7) + ((lane >> 3) & 1) * 8) * PITCH
                        + ((lane >> 4) & 1) * 16;

    uint32_t qh[4][4], ql[4][4];
    float O[8][4];
#pragma unroll
    for (int nf = 0; nf < 8; nf++)
#pragma unroll
        for (int u = 0; u < 4; u++) O[nf][u] = 0.f;
    float m0 = -1e30f, m1 = -1e30f, l0 = 0.f, l1 = 0.f;

    const int ktmax = 2 * qt + 1;
    for (int kt = 0; kt <= ktmax; kt++) {
        if (kt < ktmax) {
            issue_kv(sb + SM_KV + (uint32_t)((kt + 1) & 1) * KVSTG,
                     KH, KL, VH, VL, (kt + 1) << 6, tid);
            CP_COMMIT();
            CP_WAIT1();
        } else {
            CP_WAIT0();
        }
        __syncthreads();

        if (kt == 0) {
#pragma unroll
            for (int kc = 0; kc < 4; kc++) {
                ldsm4(qh[kc], sb + aoffQ + kc * 32);
                ldsm4(ql[kc], sb + QPL + aoffQ + kc * 32);
            }
        }

        const uint32_t st = sb + SM_KV + (uint32_t)(kt & 1) * KVSTG;

        // ---- S = Q K^T (bf16x3) ----
        float S[8][4];
#pragma unroll
        for (int nf = 0; nf < 8; nf++)
#pragma unroll
            for (int u = 0; u < 4; u++) S[nf][u] = 0.f;

        const uint32_t kb = st + boff;
#pragma unroll
        for (int kc = 0; kc < 4; kc++) {
#pragma unroll
            for (int g = 0; g < 4; g++) {
                uint32_t kh4[4], kl4[4];
                ldsm4(kh4, kb + g * 2304 + kc * 32);
                ldsm4(kl4, kb + KPL + g * 2304 + kc * 32);
                mma16816(S[2 * g],     qh[kc], kh4);
                mma16816(S[2 * g],     qh[kc], kl4);
                mma16816(S[2 * g],     ql[kc], kh4);
                mma16816(S[2 * g + 1], qh[kc], kh4 + 2);
                mma16816(S[2 * g + 1], qh[kc], kl4 + 2);
                mma16816(S[2 * g + 1], ql[kc], kh4 + 2);
            }
        }

        // ---- causal mask ----
        const int k0 = kt << 6;
        const int grow = q0 + w * 16 + (lane >> 2);
        if (k0 + 63 > q0 + w * 16) {
#pragma unroll
            for (int nf = 0; nf < 8; nf++) {
                const int gc = k0 + nf * 8 + (lane & 3) * 2;
                if (gc     > grow)     S[nf][0] = -1e9f;
                if (gc + 1 > grow)     S[nf][1] = -1e9f;
                if (gc     > grow + 8) S[nf][2] = -1e9f;
                if (gc + 1 > grow + 8) S[nf][3] = -1e9f;
            }
        }

        // ---- online softmax ----
        float rm0 = -1e30f, rm1 = -1e30f;
#pragma unroll
        for (int nf = 0; nf < 8; nf++) {
            rm0 = fmaxf(rm0, fmaxf(S[nf][0], S[nf][1]));
            rm1 = fmaxf(rm1, fmaxf(S[nf][2], S[nf][3]));
        }
        rm0 = fmaxf(rm0, __shfl_xor_sync(0xffffffffu, rm0, 1));
        rm0 = fmaxf(rm0, __shfl_xor_sync(0xffffffffu, rm0, 2));
        rm1 = fmaxf(rm1, __shfl_xor_sync(0xffffffffu, rm1, 1));
        rm1 = fmaxf(rm1, __shfl_xor_sync(0xffffffffu, rm1, 2));

        const float mn0 = fmaxf(m0, rm0), mn1 = fmaxf(m1, rm1);
        const float c0 = __expf(m0 - mn0), c1 = __expf(m1 - mn1);
        m0 = mn0; m1 = mn1;

        float rs0 = 0.f, rs1 = 0.f;
#pragma unroll
        for (int nf = 0; nf < 8; nf++) {
            S[nf][0] = __expf(S[nf][0] - mn0);
            S[nf][1] = __expf(S[nf][1] - mn0);
            S[nf][2] = __expf(S[nf][2] - mn1);
            S[nf][3] = __expf(S[nf][3] - mn1);
            rs0 += S[nf][0] + S[nf][1];
            rs1 += S[nf][2] + S[nf][3];
        }
        rs0 += __shfl_xor_sync(0xffffffffu, rs0, 1);
        rs0 += __shfl_xor_sync(0xffffffffu, rs0, 2);
        rs1 += __shfl_xor_sync(0xffffffffu, rs1, 1);
        rs1 += __shfl_xor_sync(0xffffffffu, rs1, 2);

        l0 = l0 * c0 + rs0;
        l1 = l1 * c1 + rs1;
#pragma unroll
        for (int nf = 0; nf < 8; nf++) {
            O[nf][0] *= c0; O[nf][1] *= c0;
            O[nf][2] *= c1; O[nf][3] *= c1;
        }

        // ---- O += P V (bf16x3; P frags built in registers) ----
        const uint32_t vb = st + 2 * KPL + voff;
#pragma unroll
        for (int kcp = 0; kcp < 4; kcp++) {
            uint32_t ph[4], pl[4];
            split2(S[2 * kcp][0],     S[2 * kcp][1],     ph[0], pl[0]);
            split2(S[2 * kcp][2],     S[2 * kcp][3],     ph[1], pl[1]);
            split2(S[2 * kcp + 1][0], S[2 * kcp + 1][1], ph[2], pl[2]);
            split2(S[2 * kcp + 1][2], S[2 * kcp + 1][3], ph[3], pl[3]);
#pragma unroll
            for (int g = 0; g < 4; g++) {
                uint32_t vh4[4], vl4[4];
                ldsm4t(vh4, vb + kcp * 2304 + g * 32);
                ldsm4t(vl4, vb + KPL + kcp * 2304 + g * 32);
                mma16816(O[2 * g],     ph, vh4);
                mma16816(O[2 * g],     ph, vl4);
                mma16816(O[2 * g],     pl, vh4);
                mma16816(O[2 * g + 1], ph, vh4 + 2);
                mma16816(O[2 * g + 1], ph, vl4 + 2);
                mma16816(O[2 * g + 1], pl, vh4 + 2);
            }
        }
        __syncthreads();
    }

    // ---- normalize + write merged-head fp32 [T,E] ----
    const int b = bh >> 4, h = bh & 15;
    const float i0 = 1.f / l0, i1 = 1.f / l1;
    const int r0g = q0 + w * 16 + (lane >> 2);
#pragma unroll
    for (int nf = 0; nf < 8; nf++) {
        const int d = h * HD + nf * 8 + (lane & 3) * 2;
        float2 o0 = make_float2(O[nf][0] * i0, O[nf][1] * i0);
        float2 o1 = make_float2(O[nf][2] * i1, O[nf][3] * i1);
        *(float2*)&g_x[(size_t)((size_t)b * SEQ + r0g) * EMB + d] = o0;
        *(float2*)&g_x[(size_t)((size_t)b * SEQ + r0g + 8) * EMB + d] = o1;
    }
}

// ---------------------------------------------------------------------------
extern "C" void kernel_launch(void* const* d_in, const int* in_sizes, int n_in,
                              void* d_out, int out_size)
{
    const float* v  = (const float*)d_in[0];
    const float* k  = (const float*)d_in[1];
    const float* q  = (const float*)d_in[2];
    const float* wq = (const float*)d_in[4];
    const float* bq = (const float*)d_in[5];
    const float* wk = (const float*)d_in[6];
    const float* bk = (const float*)d_in[7];
    const float* wv = (const float*)d_in[8];
    const float* bv = (const float*)d_in[9];
    const float* wo = (const float*)d_in[10];
    const float* bo = (const float*)d_in[11];
    float* out = (float*)d_out;

    cudaFuncSetAttribute(gemm_tc<0, false>, cudaFuncAttributeMaxDynamicSharedMemorySize, GEMM_SMEM);
    cudaFuncSetAttribute(gemm_tc<1, false>, cudaFuncAttributeMaxDynamicSharedMemorySize, GEMM_SMEM);
    cudaFuncSetAttribute(gemm_tc<2, false>, cudaFuncAttributeMaxDynamicSharedMemorySize, GEMM_SMEM);
    cudaFuncSetAttribute(gemm_tc<3, true>,  cudaFuncAttributeMaxDynamicSharedMemorySize, GEMM_SMEM);
    cudaFuncSetAttribute(attn_tc, cudaFuncAttributeMaxDynamicSharedMemorySize, ATTN_SMEM);

    const dim3 tblk(32, 8);
    const dim3 tgrd(EMB / 32, EMB / 32);
    const dim3 gblk(256);
    const dim3 ggrd(EMB / 128, TOK / 128);

    wtrans<<<tgrd, tblk>>>(wq);
    gemm_tc<0, false><<<ggrd, gblk, GEMM_SMEM>>>(q, bq, nullptr);
    wtrans<<<tgrd, tblk>>>(wk);
    gemm_tc<1, false><<<ggrd, gblk, GEMM_SMEM>>>(k, bk, nullptr);
    wtrans<<<tgrd, tblk>>>(wv);
    gemm_tc<2, false><<<ggrd, gblk, GEMM_SMEM>>>(v, bv, nullptr);

    attn_tc<<<dim3(SEQ / 128, BSZ * NH), gblk, ATTN_SMEM>>>();

    wtrans<<<tgrd, tblk>>>(wo);
    gemm_tc<3, true><<<ggrd, gblk, GEMM_SMEM>>>(nullptr, bo, out);
}

// round 5
// speedup vs baseline: 2.4556x; 1.0745x over previous
#include <cuda_runtime.h>
#include <cuda_bf16.h>
#include <stdint.h>
#include <math.h>

#define TOK 4096     // B*S
#define EMB 1024     // E
#define SEQ 2048     // S
#define BSZ 2        // B
#define NH  16       // heads
#define HD  64       // head dim

// Scratch (device globals — allocation-free per harness rules)
__device__ float g_x[(size_t)TOK * EMB];             // attention output [T,E]
__device__ __nv_bfloat16 g_wthi[(size_t)EMB * EMB];  // W^T hi [N,K]
__device__ __nv_bfloat16 g_wtlo[(size_t)EMB * EMB];  // W^T lo
__device__ __nv_bfloat16 g_qh[(size_t)TOK * EMB];    // Q hi [B,H,S,D] (pre-scaled)
__device__ __nv_bfloat16 g_ql[(size_t)TOK * EMB];
__device__ __nv_bfloat16 g_kh[(size_t)TOK * EMB];
__device__ __nv_bfloat16 g_kl[(size_t)TOK * EMB];
__device__ __nv_bfloat16 g_vh[(size_t)TOK * EMB];
__device__ __nv_bfloat16 g_vl[(size_t)TOK * EMB];

// ===========================================================================
// Family-safe PTX helpers (no tcgen05 — ptxas target is compute_103 family)
// ===========================================================================
__device__ __forceinline__ uint32_t smem_u32(const void* p) {
    uint32_t a;
    asm("{ .reg .u64 t; cvta.to.shared.u64 t, %1; cvt.u32.u64 %0, t; }"
        : "=r"(a) : "l"(p));
    return a;
}
__device__ __forceinline__ void ldsm4(uint32_t* r, uint32_t addr) {
    asm volatile("ldmatrix.sync.aligned.m8n8.x4.shared.b16 {%0,%1,%2,%3}, [%4];"
        : "=r"(r[0]), "=r"(r[1]), "=r"(r[2]), "=r"(r[3]) : "r"(addr));
}
__device__ __forceinline__ void ldsm4t(uint32_t* r, uint32_t addr) {
    asm volatile("ldmatrix.sync.aligned.m8n8.x4.trans.shared.b16 {%0,%1,%2,%3}, [%4];"
        : "=r"(r[0]), "=r"(r[1]), "=r"(r[2]), "=r"(r[3]) : "r"(addr));
}
__device__ __forceinline__ void mma16816(float* c, const uint32_t* a, const uint32_t* b) {
    asm volatile("mma.sync.aligned.m16n8k16.row.col.f32.bf16.bf16.f32 "
        "{%0,%1,%2,%3}, {%4,%5,%6,%7}, {%8,%9}, {%0,%1,%2,%3};"
        : "+f"(c[0]), "+f"(c[1]), "+f"(c[2]), "+f"(c[3])
        : "r"(a[0]), "r"(a[1]), "r"(a[2]), "r"(a[3]), "r"(b[0]), "r"(b[1]));
}
__device__ __forceinline__ void cp16(uint32_t dst, const void* src) {
    asm volatile("cp.async.cg.shared.global [%0], [%1], 16;" :: "r"(dst), "l"(src));
}
#define CP_COMMIT() asm volatile("cp.async.commit_group;" ::: "memory")
#define CP_WAIT0()  asm volatile("cp.async.wait_group 0;" ::: "memory")
#define CP_WAIT1()  asm volatile("cp.async.wait_group 1;" ::: "memory")

// split fp32 pair -> packed bf16 hi plane + lo plane (x low half, y high half)
__device__ __forceinline__ void split2(float x, float y, uint32_t& hi, uint32_t& lo) {
    const __nv_bfloat16 hx = __float2bfloat16_rn(x), hy = __float2bfloat16_rn(y);
    hi = ((uint32_t)__bfloat16_as_ushort(hy) << 16) | __bfloat16_as_ushort(hx);
    const __nv_bfloat16 lx = __float2bfloat16_rn(x - __bfloat162float(hx));
    const __nv_bfloat16 ly = __float2bfloat16_rn(y - __bfloat162float(hy));
    lo = ((uint32_t)__bfloat16_as_ushort(ly) << 16) | __bfloat16_as_ushort(lx);
}

// ===========================================================================
// W^T split-precision transpose: W[k][n] fp32 -> g_wthi/lo[n][k] bf16
// ===========================================================================
__global__ __launch_bounds__(256)
void wtrans(const float* __restrict__ W)
{
    __shared__ float t[32][33];
    const int tx = threadIdx.x, ty = threadIdx.y;
    const int x = blockIdx.x * 32 + tx;
#pragma unroll
    for (int j = 0; j < 4; j++)
        t[ty + 8 * j][tx] = W[(size_t)(blockIdx.y * 32 + ty + 8 * j) * EMB + x];
    __syncthreads();
    const int x2 = blockIdx.y * 32 + tx;
#pragma unroll
    for (int j = 0; j < 4; j++) {
        const float f = t[tx][ty + 8 * j];
        const __nv_bfloat16 hi = __float2bfloat16_rn(f);
        const __nv_bfloat16 lo = __float2bfloat16_rn(f - __bfloat162float(hi));
        const size_t idx = (size_t)(blockIdx.x * 32 + ty + 8 * j) * EMB + x2;
        g_wthi[idx] = hi;
        g_wtlo[idx] = lo;
    }
}

// ===========================================================================
// HMMA GEMM: C = A @ W + bias via bf16x3. 128x128 tile, BK=16, 8 warps,
// 48KB smem double-buffered -> 2 CTAs/SM. Warp tile 32x64.
// DST 0/1/2 -> bf16 hi/lo planes (q scaled by 0.125), head-split layout.
// DST 3 -> fp32 Cout row-major. SRC_GX: A = g_x.
// ===========================================================================
#define ROWB 48                        // 16 bf16 = 32B + 16B pad
#define ASZ  (128 * ROWB)              // 6144 per plane
#define STG  (4 * ASZ)                 // 24576 per stage (Ahi|Alo|Bhi|Blo)
#define GEMM_SMEM (2 * STG)            // 49152

template<int DST, bool SRC_GX>
__global__ __launch_bounds__(256, 2)
void gemm_tc(const float* __restrict__ Ain, const float* __restrict__ bias,
             float* __restrict__ Cout)
{
    extern __shared__ char smem[];
    const uint32_t sbase = smem_u32(smem);
    const float* A = SRC_GX ? g_x : Ain;

    const int tid = threadIdx.x;
    const int lane = tid & 31;
    const int wm = (tid >> 5) >> 1;
    const int wn = (tid >> 5) & 1;
    const int m0 = blockIdx.y << 7, n0 = blockIdx.x << 7;

    const uint32_t aoff = (uint32_t)(wm * 32 + (lane & 7) + ((lane >> 3) & 1) * 8) * ROWB
                        + ((lane >> 4) & 1) * 16;
    const uint32_t boff = (uint32_t)(wn * 64 + (lane & 7) + ((lane >> 4) & 1) * 8) * ROWB
                        + ((lane >> 3) & 1) * 16;

    const int row = tid >> 1;           // 0..127
    const int half = tid & 1;           // 0/1

    const float* aG = A + (size_t)(m0 + row) * EMB + half * 8;
    const __nv_bfloat16* bhG = g_wthi + (size_t)(n0 + row) * EMB + half * 8;
    const __nv_bfloat16* blG = g_wtlo + (size_t)(n0 + row) * EMB + half * 8;
    const uint32_t sts = (uint32_t)row * ROWB + half * 16;

    float c[2][8][4];
#pragma unroll
    for (int i = 0; i < 2; i++)
#pragma unroll
        for (int j = 0; j < 8; j++)
#pragma unroll
            for (int u = 0; u < 4; u++) c[i][j][u] = 0.f;

    float4 aR[2];

    // prologue: chunk 0 into stage 0
    {
        cp16(sbase + 2 * ASZ + sts, bhG);
        cp16(sbase + 3 * ASZ + sts, blG);
        CP_COMMIT();
        aR[0] = *(const float4*)(aG);
        aR[1] = *(const float4*)(aG + 4);
        uint4 uh, ul;
        split2(aR[0].x, aR[0].y, uh.x, ul.x);
        split2(aR[0].z, aR[0].w, uh.y, ul.y);
        split2(aR[1].x, aR[1].y, uh.z, ul.z);
        split2(aR[1].z, aR[1].w, uh.w, ul.w);
        *(uint4*)(smem + sts) = uh;
        *(uint4*)(smem + ASZ + sts) = ul;
        CP_WAIT0();
        __syncthreads();
    }

    const int NCH = EMB / 16;  // 64 chunks
    for (int ck = 0; ck < NCH; ck++) {
        const uint32_t cbs = sbase + (uint32_t)(ck & 1) * STG;
        const uint32_t nbs = sbase + (uint32_t)((ck + 1) & 1) * STG;
        const int koff = (ck + 1) * 16;

        if (ck + 1 < NCH) {
            cp16(nbs + 2 * ASZ + sts, bhG + koff);
            cp16(nbs + 3 * ASZ + sts, blG + koff);
            CP_COMMIT();
            aR[0] = *(const float4*)(aG + koff);
            aR[1] = *(const float4*)(aG + koff + 4);
        }

        // ---- MMA on compute stage (one k16 step) ----
        {
            uint32_t ahi[2][4], alo[2][4];
            ldsm4(ahi[0], cbs + aoff);
            ldsm4(ahi[1], cbs + aoff + 16 * ROWB);
            ldsm4(alo[0], cbs + ASZ + aoff);
            ldsm4(alo[1], cbs + ASZ + aoff + 16 * ROWB);
            uint32_t bhi[4][4], blo[4][4];
#pragma unroll
            for (int g = 0; g < 4; g++) {
                ldsm4(bhi[g], cbs + 2 * ASZ + boff + g * 16 * ROWB);
                ldsm4(blo[g], cbs + 3 * ASZ + boff + g * 16 * ROWB);
            }
#pragma unroll
            for (int mi = 0; mi < 2; mi++)
#pragma unroll
                for (int g = 0; g < 4; g++) {
                    mma16816(c[mi][2 * g],     ahi[mi], &bhi[g][0]);
                    mma16816(c[mi][2 * g],     ahi[mi], &blo[g][0]);
                    mma16816(c[mi][2 * g],     alo[mi], &bhi[g][0]);
                    mma16816(c[mi][2 * g + 1], ahi[mi], &bhi[g][2]);
                    mma16816(c[mi][2 * g + 1], ahi[mi], &blo[g][2]);
                    mma16816(c[mi][2 * g + 1], alo[mi], &bhi[g][2]);
                }
        }

        if (ck + 1 < NCH) {
            uint4 uh, ul;
            split2(aR[0].x, aR[0].y, uh.x, ul.x);
            split2(aR[0].z, aR[0].w, uh.y, ul.y);
            split2(aR[1].x, aR[1].y, uh.z, ul.z);
            split2(aR[1].z, aR[1].w, uh.w, ul.w);
            const uint32_t off = (uint32_t)((ck + 1) & 1) * STG + sts;
            *(uint4*)(smem + off) = uh;
            *(uint4*)(smem + ASZ + off) = ul;
        }
        CP_WAIT0();
        __syncthreads();
    }

    // epilogue
#pragma unroll
    for (int mi = 0; mi < 2; mi++) {
#pragma unroll
        for (int nf = 0; nf < 8; nf++) {
            const int n = n0 + wn * 64 + nf * 8 + (lane & 3) * 2;
            const float b0 = __ldg(&bias[n]), b1 = __ldg(&bias[n + 1]);
#pragma unroll
            for (int u2 = 0; u2 < 2; u2++) {
                const int m = m0 + wm * 32 + mi * 16 + (lane >> 2) + u2 * 8;
                float v0 = c[mi][nf][2 * u2]     + b0;
                float v1 = c[mi][nf][2 * u2 + 1] + b1;
                if (DST == 0) { v0 *= 0.125f; v1 *= 0.125f; }
                if (DST <= 2) {
                    __nv_bfloat16* Ch = (DST == 0) ? g_qh : (DST == 1) ? g_kh : g_vh;
                    __nv_bfloat16* Cl = (DST == 0) ? g_ql : (DST == 1) ? g_kl : g_vl;
                    uint32_t hi, lo;
                    split2(v0, v1, hi, lo);
                    const int b = m >> 11, s = m & (SEQ - 1);
                    const int h = n >> 6,  d = n & (HD - 1);
                    const size_t idx = (((size_t)b * NH + h) * SEQ + s) * HD + d;
                    *(uint32_t*)&Ch[idx] = hi;
                    *(uint32_t*)&Cl[idx] = lo;
                } else {
                    Cout[(size_t)m * EMB + n]     = v0;
                    Cout[(size_t)m * EMB + n + 1] = v1;
                }
            }
        }
    }
}

// ===========================================================================
// Causal flash attention, HMMA bf16x3. CTA: 128 q-rows x 64-key tiles,
// 8 warps x 16 rows. Q frags register-resident; K ldsm, V ldsm.trans;
// P split hi/lo in registers. KV double-buffered. (unchanged from R4)
// ===========================================================================
#define PITCH 144
#define QPL (128 * PITCH)
#define KPL (64 * PITCH)
#define SM_KV (2 * QPL)
#define KVSTG (4 * KPL)
#define ATTN_SMEM (SM_KV + 2 * KVSTG)   // 110592

__device__ __forceinline__ void issue_kv(uint32_t stg,
    const __nv_bfloat16* KH, const __nv_bfloat16* KL,
    const __nv_bfloat16* VH, const __nv_bfloat16* VL, int k0, int tid)
{
    const int r = tid >> 2, qd = tid & 3;
    const size_t srow = (size_t)(k0 + r) * HD + qd * 16;
    const uint32_t drow = (uint32_t)r * PITCH + qd * 32;
    cp16(stg + drow,                KH + srow);
    cp16(stg + drow + 16,           KH + srow + 8);
    cp16(stg + KPL + drow,          KL + srow);
    cp16(stg + KPL + drow + 16,     KL + srow + 8);
    cp16(stg + 2 * KPL + drow,      VH + srow);
    cp16(stg + 2 * KPL + drow + 16, VH + srow + 8);
    cp16(stg + 3 * KPL + drow,      VL + srow);
    cp16(stg + 3 * KPL + drow + 16, VL + srow + 8);
}

__global__ __launch_bounds__(256)
void attn_tc()
{
    extern __shared__ char smem[];
    const uint32_t sb = smem_u32(smem);
    const int tid = threadIdx.x;
    const int lane = tid & 31, w = tid >> 5;
    const int qt = blockIdx.x, bh = blockIdx.y;
    const int q0 = qt << 7;
    const size_t base = (size_t)bh * SEQ * HD;

    const __nv_bfloat16* KH = g_kh + base;
    const __nv_bfloat16* KL = g_kl + base;
    const __nv_bfloat16* VH = g_vh + base;
    const __nv_bfloat16* VL = g_vl + base;

    {
        const int r = tid >> 1, hf = tid & 1;
        const __nv_bfloat16* sh = g_qh + base + (size_t)(q0 + r) * HD + hf * 32;
        const __nv_bfloat16* sl = g_ql + base + (size_t)(q0 + r) * HD + hf * 32;
        const uint32_t dh = sb + (uint32_t)r * PITCH + hf * 64;
#pragma unroll
        for (int j = 0; j < 4; j++) {
            cp16(dh + 16 * j, sh + 8 * j);
            cp16(dh + QPL + 16 * j, sl + 8 * j);
        }
        issue_kv(sb + SM_KV, KH, KL, VH, VL, 0, tid);
        CP_COMMIT();
    }

    const uint32_t aoffQ = (uint32_t)(w * 16 + (lane & 15)) * PITCH
                         + ((lane >> 4) & 1) * 16;
    const uint32_t boff = (uint32_t)((lane & 7) + ((lane >> 4) & 1) * 8) * PITCH
                        + ((lane >> 3) & 1) * 16;
    const uint32_t voff = (uint32_t)((lane & 7) + ((lane >> 3) & 1) * 8) * PITCH
                        + ((lane >> 4) & 1) * 16;

    uint32_t qh[4][4], ql[4][4];
    float O[8][4];
#pragma unroll
    for (int nf = 0; nf < 8; nf++)
#pragma unroll
        for (int u = 0; u < 4; u++) O[nf][u] = 0.f;
    float m0 = -1e30f, m1 = -1e30f, l0 = 0.f, l1 = 0.f;

    const int ktmax = 2 * qt + 1;
    for (int kt = 0; kt <= ktmax; kt++) {
        if (kt < ktmax) {
            issue_kv(sb + SM_KV + (uint32_t)((kt + 1) & 1) * KVSTG,
                     KH, KL, VH, VL, (kt + 1) << 6, tid);
            CP_COMMIT();
            CP_WAIT1();
        } else {
            CP_WAIT0();
        }
        __syncthreads();

        if (kt == 0) {
#pragma unroll
            for (int kc = 0; kc < 4; kc++) {
                ldsm4(qh[kc], sb + aoffQ + kc * 32);
                ldsm4(ql[kc], sb + QPL + aoffQ + kc * 32);
            }
        }

        const uint32_t st = sb + SM_KV + (uint32_t)(kt & 1) * KVSTG;

        float S[8][4];
#pragma unroll
        for (int nf = 0; nf < 8; nf++)
#pragma unroll
            for (int u = 0; u < 4; u++) S[nf][u] = 0.f;

        const uint32_t kb = st + boff;
#pragma unroll
        for (int kc = 0; kc < 4; kc++) {
#pragma unroll
            for (int g = 0; g < 4; g++) {
                uint32_t kh4[4], kl4[4];
                ldsm4(kh4, kb + g * 2304 + kc * 32);
                ldsm4(kl4, kb + KPL + g * 2304 + kc * 32);
                mma16816(S[2 * g],     qh[kc], kh4);
                mma16816(S[2 * g],     qh[kc], kl4);
                mma16816(S[2 * g],     ql[kc], kh4);
                mma16816(S[2 * g + 1], qh[kc], kh4 + 2);
                mma16816(S[2 * g + 1], qh[kc], kl4 + 2);
                mma16816(S[2 * g + 1], ql[kc], kh4 + 2);
            }
        }

        const int k0 = kt << 6;
        const int grow = q0 + w * 16 + (lane >> 2);
        if (k0 + 63 > q0 + w * 16) {
#pragma unroll
            for (int nf = 0; nf < 8; nf++) {
                const int gc = k0 + nf * 8 + (lane & 3) * 2;
                if (gc     > grow)     S[nf][0] = -1e9f;
                if (gc + 1 > grow)     S[nf][1] = -1e9f;
                if (gc     > grow + 8) S[nf][2] = -1e9f;
                if (gc + 1 > grow + 8) S[nf][3] = -1e9f;
            }
        }

        float rm0 = -1e30f, rm1 = -1e30f;
#pragma unroll
        for (int nf = 0; nf < 8; nf++) {
            rm0 = fmaxf(rm0, fmaxf(S[nf][0], S[nf][1]));
            rm1 = fmaxf(rm1, fmaxf(S[nf][2], S[nf][3]));
        }
        rm0 = fmaxf(rm0, __shfl_xor_sync(0xffffffffu, rm0, 1));
        rm0 = fmaxf(rm0, __shfl_xor_sync(0xffffffffu, rm0, 2));
        rm1 = fmaxf(rm1, __shfl_xor_sync(0xffffffffu, rm1, 1));
        rm1 = fmaxf(rm1, __shfl_xor_sync(0xffffffffu, rm1, 2));

        const float mn0 = fmaxf(m0, rm0), mn1 = fmaxf(m1, rm1);
        const float c0 = __expf(m0 - mn0), c1 = __expf(m1 - mn1);
        m0 = mn0; m1 = mn1;

        float rs0 = 0.f, rs1 = 0.f;
#pragma unroll
        for (int nf = 0; nf < 8; nf++) {
            S[nf][0] = __expf(S[nf][0] - mn0);
            S[nf][1] = __expf(S[nf][1] - mn0);
            S[nf][2] = __expf(S[nf][2] - mn1);
            S[nf][3] = __expf(S[nf][3] - mn1);
            rs0 += S[nf][0] + S[nf][1];
            rs1 += S[nf][2] + S[nf][3];
        }
        rs0 += __shfl_xor_sync(0xffffffffu, rs0, 1);
        rs0 += __shfl_xor_sync(0xffffffffu, rs0, 2);
        rs1 += __shfl_xor_sync(0xffffffffu, rs1, 1);
        rs1 += __shfl_xor_sync(0xffffffffu, rs1, 2);

        l0 = l0 * c0 + rs0;
        l1 = l1 * c1 + rs1;
#pragma unroll
        for (int nf = 0; nf < 8; nf++) {
            O[nf][0] *= c0; O[nf][1] *= c0;
            O[nf][2] *= c1; O[nf][3] *= c1;
        }

        const uint32_t vb = st + 2 * KPL + voff;
#pragma unroll
        for (int kcp = 0; kcp < 4; kcp++) {
            uint32_t ph[4], pl[4];
            split2(S[2 * kcp][0],     S[2 * kcp][1],     ph[0], pl[0]);
            split2(S[2 * kcp][2],     S[2 * kcp][3],     ph[1], pl[1]);
            split2(S[2 * kcp + 1][0], S[2 * kcp + 1][1], ph[2], pl[2]);
            split2(S[2 * kcp + 1][2], S[2 * kcp + 1][3], ph[3], pl[3]);
#pragma unroll
            for (int g = 0; g < 4; g++) {
                uint32_t vh4[4], vl4[4];
                ldsm4t(vh4, vb + kcp * 2304 + g * 32);
                ldsm4t(vl4, vb + KPL + kcp * 2304 + g * 32);
                mma16816(O[2 * g],     ph, vh4);
                mma16816(O[2 * g],     ph, vl4);
                mma16816(O[2 * g],     pl, vh4);
                mma16816(O[2 * g + 1], ph, vh4 + 2);
                mma16816(O[2 * g + 1], ph, vl4 + 2);
                mma16816(O[2 * g + 1], pl, vh4 + 2);
            }
        }
        __syncthreads();
    }

    const int b = bh >> 4, h = bh & 15;
    const float i0 = 1.f / l0, i1 = 1.f / l1;
    const int r0g = q0 + w * 16 + (lane >> 2);
#pragma unroll
    for (int nf = 0; nf < 8; nf++) {
        const int d = h * HD + nf * 8 + (lane & 3) * 2;
        float2 o0 = make_float2(O[nf][0] * i0, O[nf][1] * i0);
        float2 o1 = make_float2(O[nf][2] * i1, O[nf][3] * i1);
        *(float2*)&g_x[(size_t)((size_t)b * SEQ + r0g) * EMB + d] = o0;
        *(float2*)&g_x[(size_t)((size_t)b * SEQ + r0g + 8) * EMB + d] = o1;
    }
}

// ---------------------------------------------------------------------------
extern "C" void kernel_launch(void* const* d_in, const int* in_sizes, int n_in,
                              void* d_out, int out_size)
{
    const float* v  = (const float*)d_in[0];
    const float* k  = (const float*)d_in[1];
    const float* q  = (const float*)d_in[2];
    const float* wq = (const float*)d_in[4];
    const float* bq = (const float*)d_in[5];
    const float* wk = (const float*)d_in[6];
    const float* bk = (const float*)d_in[7];
    const float* wv = (const float*)d_in[8];
    const float* bv = (const float*)d_in[9];
    const float* wo = (const float*)d_in[10];
    const float* bo = (const float*)d_in[11];
    float* out = (float*)d_out;

    cudaFuncSetAttribute(gemm_tc<0, false>, cudaFuncAttributeMaxDynamicSharedMemorySize, GEMM_SMEM);
    cudaFuncSetAttribute(gemm_tc<1, false>, cudaFuncAttributeMaxDynamicSharedMemorySize, GEMM_SMEM);
    cudaFuncSetAttribute(gemm_tc<2, false>, cudaFuncAttributeMaxDynamicSharedMemorySize, GEMM_SMEM);
    cudaFuncSetAttribute(gemm_tc<3, true>,  cudaFuncAttributeMaxDynamicSharedMemorySize, GEMM_SMEM);
    cudaFuncSetAttribute(attn_tc, cudaFuncAttributeMaxDynamicSharedMemorySize, ATTN_SMEM);

    const dim3 tblk(32, 8);
    const dim3 tgrd(EMB / 32, EMB / 32);
    const dim3 gblk(256);
    const dim3 ggrd(EMB / 128, TOK / 128);

    wtrans<<<tgrd, tblk>>>(wq);
    gemm_tc<0, false><<<ggrd, gblk, GEMM_SMEM>>>(q, bq, nullptr);
    wtrans<<<tgrd, tblk>>>(wk);
    gemm_tc<1, false><<<ggrd, gblk, GEMM_SMEM>>>(k, bk, nullptr);
    wtrans<<<tgrd, tblk>>>(wv);
    gemm_tc<2, false><<<ggrd, gblk, GEMM_SMEM>>>(v, bv, nullptr);

    attn_tc<<<dim3(SEQ / 128, BSZ * NH), gblk, ATTN_SMEM>>>();

    wtrans<<<tgrd, tblk>>>(wo);
    gemm_tc<3, true><<<ggrd, gblk, GEMM_SMEM>>>(nullptr, bo, out);
}

// round 6
// speedup vs baseline: 2.6842x; 1.0931x over previous
#include <cuda_runtime.h>
#include <cuda_bf16.h>
#include <stdint.h>
#include <math.h>

#define TOK 4096     // B*S
#define EMB 1024     // E
#define SEQ 2048     // S
#define BSZ 2        // B
#define NH  16       // heads
#define HD  64       // head dim

// Scratch (device globals — allocation-free per harness rules)
__device__ float g_x[(size_t)TOK * EMB];                 // attention output [T,E]
__device__ __nv_bfloat16 g_wthi[4 * (size_t)EMB * EMB];  // W^T hi planes q,k,v,o
__device__ __nv_bfloat16 g_wtlo[4 * (size_t)EMB * EMB];  // W^T lo planes
__device__ __nv_bfloat16 g_qh[(size_t)TOK * EMB];        // Q hi [B,H,S,D] (pre-scaled)
__device__ __nv_bfloat16 g_ql[(size_t)TOK * EMB];
__device__ __nv_bfloat16 g_kh[(size_t)TOK * EMB];
__device__ __nv_bfloat16 g_kl[(size_t)TOK * EMB];
__device__ __nv_bfloat16 g_vh[(size_t)TOK * EMB];
__device__ __nv_bfloat16 g_vl[(size_t)TOK * EMB];

// ===========================================================================
// Family-safe PTX helpers
// ===========================================================================
__device__ __forceinline__ uint32_t smem_u32(const void* p) {
    uint32_t a;
    asm("{ .reg .u64 t; cvta.to.shared.u64 t, %1; cvt.u32.u64 %0, t; }"
        : "=r"(a) : "l"(p));
    return a;
}
__device__ __forceinline__ void ldsm4(uint32_t* r, uint32_t addr) {
    asm volatile("ldmatrix.sync.aligned.m8n8.x4.shared.b16 {%0,%1,%2,%3}, [%4];"
        : "=r"(r[0]), "=r"(r[1]), "=r"(r[2]), "=r"(r[3]) : "r"(addr));
}
__device__ __forceinline__ void ldsm4t(uint32_t* r, uint32_t addr) {
    asm volatile("ldmatrix.sync.aligned.m8n8.x4.trans.shared.b16 {%0,%1,%2,%3}, [%4];"
        : "=r"(r[0]), "=r"(r[1]), "=r"(r[2]), "=r"(r[3]) : "r"(addr));
}
__device__ __forceinline__ void mma16816(float* c, const uint32_t* a, const uint32_t* b) {
    asm volatile("mma.sync.aligned.m16n8k16.row.col.f32.bf16.bf16.f32 "
        "{%0,%1,%2,%3}, {%4,%5,%6,%7}, {%8,%9}, {%0,%1,%2,%3};"
        : "+f"(c[0]), "+f"(c[1]), "+f"(c[2]), "+f"(c[3])
        : "r"(a[0]), "r"(a[1]), "r"(a[2]), "r"(a[3]), "r"(b[0]), "r"(b[1]));
}
__device__ __forceinline__ void cp16(uint32_t dst, const void* src) {
    asm volatile("cp.async.cg.shared.global [%0], [%1], 16;" :: "r"(dst), "l"(src));
}
#define CP_COMMIT() asm volatile("cp.async.commit_group;" ::: "memory")
#define CP_WAIT0()  asm volatile("cp.async.wait_group 0;" ::: "memory")
#define CP_WAIT1()  asm volatile("cp.async.wait_group 1;" ::: "memory")

__device__ __forceinline__ void split2(float x, float y, uint32_t& hi, uint32_t& lo) {
    const __nv_bfloat16 hx = __float2bfloat16_rn(x), hy = __float2bfloat16_rn(y);
    hi = ((uint32_t)__bfloat16_as_ushort(hy) << 16) | __bfloat16_as_ushort(hx);
    const __nv_bfloat16 lx = __float2bfloat16_rn(x - __bfloat162float(hx));
    const __nv_bfloat16 ly = __float2bfloat16_rn(y - __bfloat162float(hy));
    lo = ((uint32_t)__bfloat16_as_ushort(ly) << 16) | __bfloat16_as_ushort(lx);
}

// ===========================================================================
// All 4 weight transposes in one launch: W[k][n] fp32 -> planes[z][n][k] bf16
// ===========================================================================
__global__ __launch_bounds__(256)
void wtrans4(const float* __restrict__ wq, const float* __restrict__ wk,
             const float* __restrict__ wv, const float* __restrict__ wo)
{
    const int z = blockIdx.z;
    const float* W = (z == 0) ? wq : (z == 1) ? wk : (z == 2) ? wv : wo;
    __nv_bfloat16* WH = g_wthi + (size_t)z * EMB * EMB;
    __nv_bfloat16* WL = g_wtlo + (size_t)z * EMB * EMB;

    __shared__ float t[32][33];
    const int tx = threadIdx.x, ty = threadIdx.y;
    const int x = blockIdx.x * 32 + tx;
#pragma unroll
    for (int j = 0; j < 4; j++)
        t[ty + 8 * j][tx] = W[(size_t)(blockIdx.y * 32 + ty + 8 * j) * EMB + x];
    __syncthreads();
    const int x2 = blockIdx.y * 32 + tx;
#pragma unroll
    for (int j = 0; j < 4; j++) {
        const float f = t[tx][ty + 8 * j];
        const __nv_bfloat16 hi = __float2bfloat16_rn(f);
        const __nv_bfloat16 lo = __float2bfloat16_rn(f - __bfloat162float(hi));
        const size_t idx = (size_t)(blockIdx.x * 32 + ty + 8 * j) * EMB + x2;
        WH[idx] = hi;
        WL[idx] = lo;
    }
}

// ===========================================================================
// Shared GEMM mainloop pieces (BK=32, 128x128 tile, 8 warps, 2 CTAs/SM)
// ===========================================================================
#define ROWB 80
#define ASZ  (128 * ROWB)              // 10240
#define STG  (4 * ASZ)                 // 40960 (Ahi|Alo|Bhi|Blo)
#define GEMM_SMEM (2 * STG)            // 81920

// one BK=32 chunk of MMAs, pass-reordered (16 independent MMAs per pass)
__device__ __forceinline__ void mma_chunk(float c[2][8][4], uint32_t cbs,
                                          uint32_t aoff, uint32_t boff)
{
#pragma unroll
    for (int ks = 0; ks < 2; ks++) {
        uint32_t ahi[2][4], alo[2][4], bhi[4][4], blo[4][4];
        ldsm4(ahi[0], cbs + aoff + ks * 32);
        ldsm4(ahi[1], cbs + aoff + 1280 + ks * 32);
        ldsm4(alo[0], cbs + ASZ + aoff + ks * 32);
        ldsm4(alo[1], cbs + ASZ + aoff + 1280 + ks * 32);
#pragma unroll
        for (int g = 0; g < 4; g++) {
            ldsm4(bhi[g], cbs + 2 * ASZ + boff + g * 1280 + ks * 32);
            ldsm4(blo[g], cbs + 3 * ASZ + boff + g * 1280 + ks * 32);
        }
        // pass 1: hi*hi
#pragma unroll
        for (int mi = 0; mi < 2; mi++)
#pragma unroll
            for (int g = 0; g < 4; g++) {
                mma16816(c[mi][2 * g],     ahi[mi], &bhi[g][0]);
                mma16816(c[mi][2 * g + 1], ahi[mi], &bhi[g][2]);
            }
        // pass 2: hi*lo
#pragma unroll
        for (int mi = 0; mi < 2; mi++)
#pragma unroll
            for (int g = 0; g < 4; g++) {
                mma16816(c[mi][2 * g],     ahi[mi], &blo[g][0]);
                mma16816(c[mi][2 * g + 1], ahi[mi], &blo[g][2]);
            }
        // pass 3: lo*hi
#pragma unroll
        for (int mi = 0; mi < 2; mi++)
#pragma unroll
            for (int g = 0; g < 4; g++) {
                mma16816(c[mi][2 * g],     alo[mi], &bhi[g][0]);
                mma16816(c[mi][2 * g + 1], alo[mi], &bhi[g][2]);
            }
    }
}

__device__ __forceinline__ void stage_a(char* smem, uint32_t off, const float4* aR)
{
#pragma unroll
    for (int i = 0; i < 4; i++) {
        uint2 uh, ul;
        split2(aR[i].x, aR[i].y, uh.x, ul.x);
        split2(aR[i].z, aR[i].w, uh.y, ul.y);
        *(uint2*)(smem + off + 8 * i) = uh;
        *(uint2*)(smem + ASZ + off + 8 * i) = ul;
    }
}

// ===========================================================================
// Fused Q/K/V projection: blockIdx.z selects input/weight/bias/dst planes
// ===========================================================================
__global__ __launch_bounds__(256, 2)
void gemm_qkv(const float* __restrict__ q, const float* __restrict__ k,
              const float* __restrict__ v, const float* __restrict__ bq,
              const float* __restrict__ bk, const float* __restrict__ bv)
{
    extern __shared__ char smem[];
    const uint32_t sbase = smem_u32(smem);
    const int z = blockIdx.z;
    const float* A    = (z == 0) ? q  : (z == 1) ? k  : v;
    const float* bias = (z == 0) ? bq : (z == 1) ? bk : bv;
    const __nv_bfloat16* WHg = g_wthi + (size_t)z * EMB * EMB;
    const __nv_bfloat16* WLg = g_wtlo + (size_t)z * EMB * EMB;
    __nv_bfloat16* Ch = (z == 0) ? g_qh : (z == 1) ? g_kh : g_vh;
    __nv_bfloat16* Cl = (z == 0) ? g_ql : (z == 1) ? g_kl : g_vl;
    const float oscale = (z == 0) ? 0.125f : 1.0f;

    const int tid = threadIdx.x;
    const int lane = tid & 31;
    const int wm = (tid >> 5) >> 1, wn = (tid >> 5) & 1;
    const int m0 = blockIdx.y << 7, n0 = blockIdx.x << 7;

    const uint32_t aoff = (uint32_t)(wm * 32 + (lane & 7) + ((lane >> 3) & 1) * 8) * ROWB
                        + ((lane >> 4) & 1) * 16;
    const uint32_t boff = (uint32_t)(wn * 64 + (lane & 7) + ((lane >> 4) & 1) * 8) * ROWB
                        + ((lane >> 3) & 1) * 16;

    const int row = tid >> 1, half = tid & 1;
    const float* aG = A + (size_t)(m0 + row) * EMB + half * 16;
    const __nv_bfloat16* bhG = WHg + (size_t)(n0 + row) * EMB + half * 16;
    const __nv_bfloat16* blG = WLg + (size_t)(n0 + row) * EMB + half * 16;
    const uint32_t sts = (uint32_t)row * ROWB + half * 32;

    float c[2][8][4];
#pragma unroll
    for (int i = 0; i < 2; i++)
#pragma unroll
        for (int j = 0; j < 8; j++)
#pragma unroll
            for (int u = 0; u < 4; u++) c[i][j][u] = 0.f;

    float4 aR[4];
    // prologue
    {
#pragma unroll
        for (int j = 0; j < 2; j++) {
            cp16(sbase + 2 * ASZ + sts + 16 * j, bhG + 8 * j);
            cp16(sbase + 3 * ASZ + sts + 16 * j, blG + 8 * j);
        }
        CP_COMMIT();
#pragma unroll
        for (int i = 0; i < 4; i++) aR[i] = *(const float4*)(aG + 4 * i);
        stage_a(smem, sts, aR);
        CP_WAIT0();
        __syncthreads();
    }

    const int NCH = EMB / 32;
    for (int ck = 0; ck < NCH; ck++) {
        const uint32_t cbs = sbase + (uint32_t)(ck & 1) * STG;
        const uint32_t nbs = sbase + (uint32_t)((ck + 1) & 1) * STG;
        const int koff = (ck + 1) * 32;

        if (ck + 1 < NCH) {
#pragma unroll
            for (int j = 0; j < 2; j++) {
                cp16(nbs + 2 * ASZ + sts + 16 * j, bhG + koff + 8 * j);
                cp16(nbs + 3 * ASZ + sts + 16 * j, blG + koff + 8 * j);
            }
            CP_COMMIT();
#pragma unroll
            for (int i = 0; i < 4; i++)
                aR[i] = *(const float4*)(aG + koff + 4 * i);
        }

        mma_chunk(c, cbs, aoff, boff);

        if (ck + 1 < NCH)
            stage_a(smem, (uint32_t)((ck + 1) & 1) * STG + sts, aR);
        CP_WAIT0();
        __syncthreads();
    }

    // epilogue: bf16 hi/lo planes, head-split [B,H,S,D]
#pragma unroll
    for (int mi = 0; mi < 2; mi++) {
#pragma unroll
        for (int nf = 0; nf < 8; nf++) {
            const int n = n0 + wn * 64 + nf * 8 + (lane & 3) * 2;
            const float b0 = __ldg(&bias[n]), b1 = __ldg(&bias[n + 1]);
#pragma unroll
            for (int u2 = 0; u2 < 2; u2++) {
                const int m = m0 + wm * 32 + mi * 16 + (lane >> 2) + u2 * 8;
                const float v0 = (c[mi][nf][2 * u2]     + b0) * oscale;
                const float v1 = (c[mi][nf][2 * u2 + 1] + b1) * oscale;
                uint32_t hi, lo;
                split2(v0, v1, hi, lo);
                const int b = m >> 11, s = m & (SEQ - 1);
                const int h = n >> 6,  d = n & (HD - 1);
                const size_t idx = (((size_t)b * NH + h) * SEQ + s) * HD + d;
                *(uint32_t*)&Ch[idx] = hi;
                *(uint32_t*)&Cl[idx] = lo;
            }
        }
    }
}

// ===========================================================================
// Output projection: A = g_x, weight plane 3, fp32 out
// ===========================================================================
__global__ __launch_bounds__(256, 2)
void gemm_o(const float* __restrict__ bias, float* __restrict__ Cout)
{
    extern __shared__ char smem[];
    const uint32_t sbase = smem_u32(smem);
    const float* A = g_x;
    const __nv_bfloat16* WHg = g_wthi + 3 * (size_t)EMB * EMB;
    const __nv_bfloat16* WLg = g_wtlo + 3 * (size_t)EMB * EMB;

    const int tid = threadIdx.x;
    const int lane = tid & 31;
    const int wm = (tid >> 5) >> 1, wn = (tid >> 5) & 1;
    const int m0 = blockIdx.y << 7, n0 = blockIdx.x << 7;

    const uint32_t aoff = (uint32_t)(wm * 32 + (lane & 7) + ((lane >> 3) & 1) * 8) * ROWB
                        + ((lane >> 4) & 1) * 16;
    const uint32_t boff = (uint32_t)(wn * 64 + (lane & 7) + ((lane >> 4) & 1) * 8) * ROWB
                        + ((lane >> 3) & 1) * 16;

    const int row = tid >> 1, half = tid & 1;
    const float* aG = A + (size_t)(m0 + row) * EMB + half * 16;
    const __nv_bfloat16* bhG = WHg + (size_t)(n0 + row) * EMB + half * 16;
    const __nv_bfloat16* blG = WLg + (size_t)(n0 + row) * EMB + half * 16;
    const uint32_t sts = (uint32_t)row * ROWB + half * 32;

    float c[2][8][4];
#pragma unroll
    for (int i = 0; i < 2; i++)
#pragma unroll
        for (int j = 0; j < 8; j++)
#pragma unroll
            for (int u = 0; u < 4; u++) c[i][j][u] = 0.f;

    float4 aR[4];
    {
#pragma unroll
        for (int j = 0; j < 2; j++) {
            cp16(sbase + 2 * ASZ + sts + 16 * j, bhG + 8 * j);
            cp16(sbase + 3 * ASZ + sts + 16 * j, blG + 8 * j);
        }
        CP_COMMIT();
#pragma unroll
        for (int i = 0; i < 4; i++) aR[i] = *(const float4*)(aG + 4 * i);
        stage_a(smem, sts, aR);
        CP_WAIT0();
        __syncthreads();
    }

    const int NCH = EMB / 32;
    for (int ck = 0; ck < NCH; ck++) {
        const uint32_t cbs = sbase + (uint32_t)(ck & 1) * STG;
        const uint32_t nbs = sbase + (uint32_t)((ck + 1) & 1) * STG;
        const int koff = (ck + 1) * 32;

        if (ck + 1 < NCH) {
#pragma unroll
            for (int j = 0; j < 2; j++) {
                cp16(nbs + 2 * ASZ + sts + 16 * j, bhG + koff + 8 * j);
                cp16(nbs + 3 * ASZ + sts + 16 * j, blG + koff + 8 * j);
            }
            CP_COMMIT();
#pragma unroll
            for (int i = 0; i < 4; i++)
                aR[i] = *(const float4*)(aG + koff + 4 * i);
        }

        mma_chunk(c, cbs, aoff, boff);

        if (ck + 1 < NCH)
            stage_a(smem, (uint32_t)((ck + 1) & 1) * STG + sts, aR);
        CP_WAIT0();
        __syncthreads();
    }

#pragma unroll
    for (int mi = 0; mi < 2; mi++) {
#pragma unroll
        for (int nf = 0; nf < 8; nf++) {
            const int n = n0 + wn * 64 + nf * 8 + (lane & 3) * 2;
            const float b0 = __ldg(&bias[n]), b1 = __ldg(&bias[n + 1]);
#pragma unroll
            for (int u2 = 0; u2 < 2; u2++) {
                const int m = m0 + wm * 32 + mi * 16 + (lane >> 2) + u2 * 8;
                Cout[(size_t)m * EMB + n]     = c[mi][nf][2 * u2]     + b0;
                Cout[(size_t)m * EMB + n + 1] = c[mi][nf][2 * u2 + 1] + b1;
            }
        }
    }
}

// ===========================================================================
// Causal flash attention, HMMA bf16x3 (longest-tiles-first scheduling)
// ===========================================================================
#define PITCH 144
#define QPL (128 * PITCH)
#define KPL (64 * PITCH)
#define SM_KV (2 * QPL)
#define KVSTG (4 * KPL)
#define ATTN_SMEM (SM_KV + 2 * KVSTG)   // 110592

__device__ __forceinline__ void issue_kv(uint32_t stg,
    const __nv_bfloat16* KH, const __nv_bfloat16* KL,
    const __nv_bfloat16* VH, const __nv_bfloat16* VL, int k0, int tid)
{
    const int r = tid >> 2, qd = tid & 3;
    const size_t srow = (size_t)(k0 + r) * HD + qd * 16;
    const uint32_t drow = (uint32_t)r * PITCH + qd * 32;
    cp16(stg + drow,                KH + srow);
    cp16(stg + drow + 16,           KH + srow + 8);
    cp16(stg + KPL + drow,          KL + srow);
    cp16(stg + KPL + drow + 16,     KL + srow + 8);
    cp16(stg + 2 * KPL + drow,      VH + srow);
    cp16(stg + 2 * KPL + drow + 16, VH + srow + 8);
    cp16(stg + 3 * KPL + drow,      VL + srow);
    cp16(stg + 3 * KPL + drow + 16, VL + srow + 8);
}

__global__ __launch_bounds__(256)
void attn_tc()
{
    extern __shared__ char smem[];
    const uint32_t sb = smem_u32(smem);
    const int tid = threadIdx.x;
    const int lane = tid & 31, w = tid >> 5;
    const int qt = gridDim.x - 1 - blockIdx.x;   // longest first
    const int bh = blockIdx.y;
    const int q0 = qt << 7;
    const size_t base = (size_t)bh * SEQ * HD;

    const __nv_bfloat16* KH = g_kh + base;
    const __nv_bfloat16* KL = g_kl + base;
    const __nv_bfloat16* VH = g_vh + base;
    const __nv_bfloat16* VL = g_vl + base;

    {
        const int r = tid >> 1, hf = tid & 1;
        const __nv_bfloat16* sh = g_qh + base + (size_t)(q0 + r) * HD + hf * 32;
        const __nv_bfloat16* sl = g_ql + base + (size_t)(q0 + r) * HD + hf * 32;
        const uint32_t dh = sb + (uint32_t)r * PITCH + hf * 64;
#pragma unroll
        for (int j = 0; j < 4; j++) {
            cp16(dh + 16 * j, sh + 8 * j);
            cp16(dh + QPL + 16 * j, sl + 8 * j);
        }
        issue_kv(sb + SM_KV, KH, KL, VH, VL, 0, tid);
        CP_COMMIT();
    }

    const uint32_t aoffQ = (uint32_t)(w * 16 + (lane & 15)) * PITCH
                         + ((lane >> 4) & 1) * 16;
    const uint32_t boff = (uint32_t)((lane & 7) + ((lane >> 4) & 1) * 8) * PITCH
                        + ((lane >> 3) & 1) * 16;
    const uint32_t voff = (uint32_t)((lane & 7) + ((lane >> 3) & 1) * 8) * PITCH
                        + ((lane >> 4) & 1) * 16;

    uint32_t qh[4][4], ql[4][4];
    float O[8][4];
#pragma unroll
    for (int nf = 0; nf < 8; nf++)
#pragma unroll
        for (int u = 0; u < 4; u++) O[nf][u] = 0.f;
    float m0 = -1e30f, m1 = -1e30f, l0 = 0.f, l1 = 0.f;

    const int ktmax = 2 * qt + 1;
    for (int kt = 0; kt <= ktmax; kt++) {
        if (kt < ktmax) {
            issue_kv(sb + SM_KV + (uint32_t)((kt + 1) & 1) * KVSTG,
                     KH, KL, VH, VL, (kt + 1) << 6, tid);
            CP_COMMIT();
            CP_WAIT1();
        } else {
            CP_WAIT0();
        }
        __syncthreads();

        if (kt == 0) {
#pragma unroll
            for (int kc = 0; kc < 4; kc++) {
                ldsm4(qh[kc], sb + aoffQ + kc * 32);
                ldsm4(ql[kc], sb + QPL + aoffQ + kc * 32);
            }
        }

        const uint32_t st = sb + SM_KV + (uint32_t)(kt & 1) * KVSTG;

        float S[8][4];
#pragma unroll
        for (int nf = 0; nf < 8; nf++)
#pragma unroll
            for (int u = 0; u < 4; u++) S[nf][u] = 0.f;

        const uint32_t kb = st + boff;
#pragma unroll
        for (int kc = 0; kc < 4; kc++) {
#pragma unroll
            for (int g = 0; g < 4; g++) {
                uint32_t kh4[4], kl4[4];
                ldsm4(kh4, kb + g * 2304 + kc * 32);
                ldsm4(kl4, kb + KPL + g * 2304 + kc * 32);
                mma16816(S[2 * g],     qh[kc], kh4);
                mma16816(S[2 * g],     qh[kc], kl4);
                mma16816(S[2 * g],     ql[kc], kh4);
                mma16816(S[2 * g + 1], qh[kc], kh4 + 2);
                mma16816(S[2 * g + 1], qh[kc], kl4 + 2);
                mma16816(S[2 * g + 1], ql[kc], kh4 + 2);
            }
        }

        const int k0 = kt << 6;
        const int grow = q0 + w * 16 + (lane >> 2);
        if (k0 + 63 > q0 + w * 16) {
#pragma unroll
            for (int nf = 0; nf < 8; nf++) {
                const int gc = k0 + nf * 8 + (lane & 3) * 2;
                if (gc     > grow)     S[nf][0] = -1e9f;
                if (gc + 1 > grow)     S[nf][1] = -1e9f;
                if (gc     > grow + 8) S[nf][2] = -1e9f;
                if (gc + 1 > grow + 8) S[nf][3] = -1e9f;
            }
        }

        float rm0 = -1e30f, rm1 = -1e30f;
#pragma unroll
        for (int nf = 0; nf < 8; nf++) {
            rm0 = fmaxf(rm0, fmaxf(S[nf][0], S[nf][1]));
            rm1 = fmaxf(rm1, fmaxf(S[nf][2], S[nf][3]));
        }
        rm0 = fmaxf(rm0, __shfl_xor_sync(0xffffffffu, rm0, 1));
        rm0 = fmaxf(rm0, __shfl_xor_sync(0xffffffffu, rm0, 2));
        rm1 = fmaxf(rm1, __shfl_xor_sync(0xffffffffu, rm1, 1));
        rm1 = fmaxf(rm1, __shfl_xor_sync(0xffffffffu, rm1, 2));

        const float mn0 = fmaxf(m0, rm0), mn1 = fmaxf(m1, rm1);
        const float c0 = __expf(m0 - mn0), c1 = __expf(m1 - mn1);
        m0 = mn0; m1 = mn1;

        float rs0 = 0.f, rs1 = 0.f;
#pragma unroll
        for (int nf = 0; nf < 8; nf++) {
            S[nf][0] = __expf(S[nf][0] - mn0);
            S[nf][1] = __expf(S[nf][1] - mn0);
            S[nf][2] = __expf(S[nf][2] - mn1);
            S[nf][3] = __expf(S[nf][3] - mn1);
            rs0 += S[nf][0] + S[nf][1];
            rs1 += S[nf][2] + S[nf][3];
        }
        rs0 += __shfl_xor_sync(0xffffffffu, rs0, 1);
        rs0 += __shfl_xor_sync(0xffffffffu, rs0, 2);
        rs1 += __shfl_xor_sync(0xffffffffu, rs1, 1);
        rs1 += __shfl_xor_sync(0xffffffffu, rs1, 2);

        l0 = l0 * c0 + rs0;
        l1 = l1 * c1 + rs1;
#pragma unroll
        for (int nf = 0; nf < 8; nf++) {
            O[nf][0] *= c0; O[nf][1] *= c0;
            O[nf][2] *= c1; O[nf][3] *= c1;
        }

        const uint32_t vb = st + 2 * KPL + voff;
#pragma unroll
        for (int kcp = 0; kcp < 4; kcp++) {
            uint32_t ph[4], pl[4];
            split2(S[2 * kcp][0],     S[2 * kcp][1],     ph[0], pl[0]);
            split2(S[2 * kcp][2],     S[2 * kcp][3],     ph[1], pl[1]);
            split2(S[2 * kcp + 1][0], S[2 * kcp + 1][1], ph[2], pl[2]);
            split2(S[2 * kcp + 1][2], S[2 * kcp + 1][3], ph[3], pl[3]);
#pragma unroll
            for (int g = 0; g < 4; g++) {
                uint32_t vh4[4], vl4[4];
                ldsm4t(vh4, vb + kcp * 2304 + g * 32);
                ldsm4t(vl4, vb + KPL + kcp * 2304 + g * 32);
                mma16816(O[2 * g],     ph, vh4);
                mma16816(O[2 * g],     ph, vl4);
                mma16816(O[2 * g],     pl, vh4);
                mma16816(O[2 * g + 1], ph, vh4 + 2);
                mma16816(O[2 * g + 1], ph, vl4 + 2);
                mma16816(O[2 * g + 1], pl, vh4 + 2);
            }
        }
        __syncthreads();
    }

    const int b = bh >> 4, h = bh & 15;
    const float i0 = 1.f / l0, i1 = 1.f / l1;
    const int r0g = q0 + w * 16 + (lane >> 2);
#pragma unroll
    for (int nf = 0; nf < 8; nf++) {
        const int d = h * HD + nf * 8 + (lane & 3) * 2;
        float2 o0 = make_float2(O[nf][0] * i0, O[nf][1] * i0);
        float2 o1 = make_float2(O[nf][2] * i1, O[nf][3] * i1);
        *(float2*)&g_x[(size_t)((size_t)b * SEQ + r0g) * EMB + d] = o0;
        *(float2*)&g_x[(size_t)((size_t)b * SEQ + r0g + 8) * EMB + d] = o1;
    }
}

// ---------------------------------------------------------------------------
extern "C" void kernel_launch(void* const* d_in, const int* in_sizes, int n_in,
                              void* d_out, int out_size)
{
    const float* v  = (const float*)d_in[0];
    const float* k  = (const float*)d_in[1];
    const float* q  = (const float*)d_in[2];
    const float* wq = (const float*)d_in[4];
    const float* bq = (const float*)d_in[5];
    const float* wk = (const float*)d_in[6];
    const float* bk = (const float*)d_in[7];
    const float* wv = (const float*)d_in[8];
    const float* bv = (const float*)d_in[9];
    const float* wo = (const float*)d_in[10];
    const float* bo = (const float*)d_in[11];
    float* out = (float*)d_out;

    cudaFuncSetAttribute(gemm_qkv, cudaFuncAttributeMaxDynamicSharedMemorySize, GEMM_SMEM);
    cudaFuncSetAttribute(gemm_o,   cudaFuncAttributeMaxDynamicSharedMemorySize, GEMM_SMEM);
    cudaFuncSetAttribute(attn_tc,  cudaFuncAttributeMaxDynamicSharedMemorySize, ATTN_SMEM);

    wtrans4<<<dim3(EMB / 32, EMB / 32, 4), dim3(32, 8)>>>(wq, wk, wv, wo);
    gemm_qkv<<<dim3(EMB / 128, TOK / 128, 3), 256, GEMM_SMEM>>>(q, k, v, bq, bk, bv);
    attn_tc<<<dim3(SEQ / 128, BSZ * NH), 256, ATTN_SMEM>>>();
    gemm_o<<<dim3(EMB / 128, TOK / 128), 256, GEMM_SMEM>>>(bo, out);
}